// round 9
// baseline (speedup 1.0000x reference)
#include <cuda_runtime.h>
#include <cuda_bf16.h>
#include <mma.h>
#include <stdint.h>

using namespace nvcuda;

#define NCN 100000
#define NRN 100000
#define HD  64
#define EMAX 2000000
#define SCAN_BS 256
#define NSCANB 391   // ceil(100000/256)

// ---------------- scratch (device globals: allocation-free) ----------------
__device__ float g_t_c[(size_t)NCN * HD];
__device__ float g_t_r[(size_t)NRN * HD];
__device__ float g_s_r[(size_t)NRN * HD];
__device__ float g_s_c[(size_t)NCN * HD];
__device__ float g_h_r[(size_t)NRN * HD];
__device__ float g_h_c[(size_t)NCN * HD];
__device__ int   g_dg_r[NRN];
__device__ int   g_dg_c[NCN];
__device__ int   g_off_r[NRN];
__device__ int   g_off_c[NCN];
__device__ int   g_cur_r[NRN];
__device__ int   g_cur_c[NCN];
__device__ int   g_csr_cr[EMAX];   // pre-scaled src*16 (float4 index)
__device__ int   g_csr_rc[EMAX];
__device__ int   g_bsum[2 * NSCANB + 2];
// folded decoder weights/biases
__device__ float g_wc_crl[HD * HD];
__device__ float g_wc_crr[HD * HD];
__device__ float g_wc_rcl[HD * HD];
__device__ float g_wc_rcr[HD * HD];
__device__ float g_bc_r[HD];
__device__ float g_bc_c[HD];

// ---------------- kernels ----------------

__global__ void zero2_k(int4* __restrict__ a, int4* __restrict__ b, int n4) {
    int i = blockIdx.x * blockDim.x + threadIdx.x;
    if (i < n4) a[i] = make_int4(0, 0, 0, 0);
    else if (i < 2 * n4) b[i - n4] = make_int4(0, 0, 0, 0);
}

__global__ void degree2_k(const int* __restrict__ dstA, int* __restrict__ degA,
                          const int* __restrict__ dstB, int* __restrict__ degB, int nE) {
    int i = blockIdx.x * blockDim.x + threadIdx.x;
    if (i < nE) atomicAdd(degA + __ldg(dstA + i), 1);
    else if (i < 2 * nE) atomicAdd(degB + __ldg(dstB + (i - nE)), 1);
}

// --- segmented 3-kernel exclusive scan: segment 0 = relation A, 1 = relation B ---
__global__ void scan_block2_k(const int* __restrict__ inA, int* __restrict__ outA,
                              const int* __restrict__ inB, int* __restrict__ outB,
                              int* __restrict__ bsum, int n) {
    __shared__ int sh[SCAN_BS];
    int b = blockIdx.x;
    const int* in;
    int* out;
    int lb;
    if (b < NSCANB) { in = inA; out = outA; lb = b; }
    else            { in = inB; out = outB; lb = b - NSCANB; }
    int i = lb * SCAN_BS + threadIdx.x;
    int v = (i < n) ? in[i] : 0;
    sh[threadIdx.x] = v;
    __syncthreads();
    for (int off = 1; off < SCAN_BS; off <<= 1) {
        int t = (threadIdx.x >= off) ? sh[threadIdx.x - off] : 0;
        __syncthreads();
        sh[threadIdx.x] += t;
        __syncthreads();
    }
    if (i < n) out[i] = sh[threadIdx.x] - v;
    if (threadIdx.x == SCAN_BS - 1) bsum[b] = sh[threadIdx.x];
}

__global__ void scan_sums2_k(int* __restrict__ bsum) {
    __shared__ int sh[1024];
    int v = (threadIdx.x < NSCANB) ? bsum[blockIdx.x * NSCANB + threadIdx.x] : 0;
    sh[threadIdx.x] = v;
    __syncthreads();
    for (int off = 1; off < 1024; off <<= 1) {
        int t = (threadIdx.x >= off) ? sh[threadIdx.x - off] : 0;
        __syncthreads();
        sh[threadIdx.x] += t;
        __syncthreads();
    }
    if (threadIdx.x < NSCANB) bsum[blockIdx.x * NSCANB + threadIdx.x] = sh[threadIdx.x] - v;
}

__global__ void scan_add_copy2_k(int* __restrict__ outA, int* __restrict__ curA,
                                 int* __restrict__ outB, int* __restrict__ curB,
                                 const int* __restrict__ bsum, int n) {
    int b = blockIdx.x;
    int* out;
    int* cur;
    int lb;
    if (b < NSCANB) { out = outA; cur = curA; lb = b; }
    else            { out = outB; cur = curB; lb = b - NSCANB; }
    int i = lb * SCAN_BS + threadIdx.x;
    if (i < n) {
        int v = out[i] + bsum[b];
        out[i] = v;
        cur[i] = v;
    }
}

// both relations' CSR fill; stores src*16 (float4 row base index)
__global__ void csr_fill2_k(const int* __restrict__ srcA, const int* __restrict__ dstA,
                            int* __restrict__ curA, int* __restrict__ csrA,
                            const int* __restrict__ srcB, const int* __restrict__ dstB,
                            int* __restrict__ curB, int* __restrict__ csrB, int nE) {
    int i = blockIdx.x * blockDim.x + threadIdx.x;
    if (i < nE) {
        int d = __ldg(dstA + i);
        int p = atomicAdd(curA + d, 1);
        csrA[p] = __ldg(srcA + i) << 4;
    } else if (i < 2 * nE) {
        int j = i - nE;
        int d = __ldg(dstB + j);
        int p = atomicAdd(curB + d, 1);
        csrB[p] = __ldg(srcB + j) << 4;
    }
}

// One launch for the whole decoder fold (258 blocks of 64 threads).
__global__ void fold_k(const float* __restrict__ W2crl, const float* __restrict__ W2crr,
                       const float* __restrict__ W2rcl, const float* __restrict__ W2rcr,
                       const float* __restrict__ b2cr,  const float* __restrict__ b2rc,
                       const float* __restrict__ Wd_top, const float* __restrict__ Wd_bot,
                       float* __restrict__ wc_crl, float* __restrict__ wc_crr,
                       float* __restrict__ wc_rcl, float* __restrict__ wc_rcr,
                       float* __restrict__ bc_r, float* __restrict__ bc_c) {
    __shared__ float Ar[HD];
    int b = blockIdx.x, j = threadIdx.x;
    const float *Arow, *B;
    float* Crow;
    if (b < 256) {
        int which = b >> 6, r = b & 63;
        switch (which) {
            case 0: Arow = W2crl + r * HD; B = Wd_bot; Crow = wc_crl + r * HD; break;
            case 1: Arow = W2crr + r * HD; B = Wd_bot; Crow = wc_crr + r * HD; break;
            case 2: Arow = W2rcl + r * HD; B = Wd_top; Crow = wc_rcl + r * HD; break;
            default:Arow = W2rcr + r * HD; B = Wd_top; Crow = wc_rcr + r * HD; break;
        }
    } else if (b == 256) { Arow = b2cr; B = Wd_bot; Crow = bc_r; }
    else                 { Arow = b2rc; B = Wd_top; Crow = bc_c; }
    Ar[j] = Arow[j];
    __syncthreads();
    float s = 0.f;
#pragma unroll 16
    for (int k = 0; k < HD; k++) s += Ar[k] * B[k * HD + j];
    Crow[j] = s;
}

// truncate fp32 -> tf32-representable (10 explicit mantissa bits)
__device__ __forceinline__ float tf32_hi(float x) {
    return __uint_as_float(__float_as_uint(x) & 0xFFFFE000u);
}

// Y[n,64] = X[n,K] @ W[K,64] via 3xTF32 wmma, v2:
//  - W split hi/lo staged in smem once per block
//  - X staged + split in smem per 32-wide K chunk (coalesced, shared across warps)
// Block = 32 rows x 64 cols; 8 warps: rt = warp>>2 (16-row tile), ct = warp&3 (16-col tile).
// Requires n % 32 == 0, K % 32 == 0, blockDim.x == 256.
__global__ void gemm_tf32_k(const float* __restrict__ X, const float* __restrict__ W,
                            float* __restrict__ Y, int K) {
    extern __shared__ float sm[];
    float* Whi = sm;                    // K*64
    float* Wlo = Whi + K * HD;          // K*64
    float* Xhi = Wlo + K * HD;          // 32*32
    float* Xlo = Xhi + 32 * 32;         // 32*32
    for (int i = threadIdx.x; i < K * HD; i += 256) {
        float w = W[i];
        float hi = tf32_hi(w);
        Whi[i] = hi;
        Wlo[i] = tf32_hi(w - hi);
    }
    int warp = threadIdx.x >> 5;
    int rt = warp >> 2, ct = warp & 3;
    int row0 = blockIdx.x * 32;

    wmma::fragment<wmma::accumulator, 16, 16, 8, float> acc;
    wmma::fill_fragment(acc, 0.f);
    wmma::fragment<wmma::matrix_a, 16, 16, 8, wmma::precision::tf32, wmma::row_major> a_hi, a_lo;
    wmma::fragment<wmma::matrix_b, 16, 16, 8, wmma::precision::tf32, wmma::row_major> b_hi, b_lo;

    for (int kc = 0; kc < K; kc += 32) {
        // stage + split 32x32 X chunk (4 elems/thread, coalesced along k)
#pragma unroll
        for (int j = 0; j < 4; j++) {
            int idx = threadIdx.x + j * 256;
            int r = idx >> 5, c = idx & 31;
            float v = __ldg(X + (size_t)(row0 + r) * K + kc + c);
            float hi = tf32_hi(v);
            Xhi[idx] = hi;
            Xlo[idx] = tf32_hi(v - hi);
        }
        __syncthreads();
#pragma unroll
        for (int ks = 0; ks < 32; ks += 8) {
            wmma::load_matrix_sync(a_hi, Xhi + (rt * 16) * 32 + ks, 32);
            wmma::load_matrix_sync(a_lo, Xlo + (rt * 16) * 32 + ks, 32);
            wmma::load_matrix_sync(b_hi, Whi + (kc + ks) * HD + ct * 16, HD);
            wmma::load_matrix_sync(b_lo, Wlo + (kc + ks) * HD + ct * 16, HD);
            wmma::mma_sync(acc, a_hi, b_hi, acc);
            wmma::mma_sync(acc, a_hi, b_lo, acc);
            wmma::mma_sync(acc, a_lo, b_hi, acc);
        }
        __syncthreads();
    }
    wmma::store_matrix_sync(Y + (size_t)(row0 + rt * 16) * HD + ct * 16, acc, HD,
                            wmma::mem_row_major);
}

// Fused gather-aggregate + mean + self + bias (+relu).
// 16 lanes per dst node (float4 per lane); csr holds pre-scaled src*16; unroll-2.
__global__ void aggregate16_k(const float* __restrict__ feat, const float* __restrict__ self,
                              const float* __restrict__ bias, const int* __restrict__ offs,
                              const int* __restrict__ deg, const int* __restrict__ csr,
                              float* __restrict__ out, int n, int do_relu) {
    int g = (blockIdx.x * blockDim.x + threadIdx.x) >> 4;
    int l = threadIdx.x & 15;
    if (g >= n) return;
    int beg = __ldg(offs + g);
    int dg  = __ldg(deg + g);
    int end = beg + dg;
    const float4* feat4 = reinterpret_cast<const float4*>(feat);
    float4 a0 = make_float4(0.f, 0.f, 0.f, 0.f);
    float4 a1 = make_float4(0.f, 0.f, 0.f, 0.f);
    int e = beg;
    for (; e + 1 < end; e += 2) {
        int s0 = __ldg(csr + e);
        int s1 = __ldg(csr + e + 1);
        float4 v0 = feat4[s0 + l];
        float4 v1 = feat4[s1 + l];
        a0.x += v0.x; a0.y += v0.y; a0.z += v0.z; a0.w += v0.w;
        a1.x += v1.x; a1.y += v1.y; a1.z += v1.z; a1.w += v1.w;
    }
    if (e < end) {
        int s0 = __ldg(csr + e);
        float4 v0 = feat4[s0 + l];
        a0.x += v0.x; a0.y += v0.y; a0.z += v0.z; a0.w += v0.w;
    }
    float inv = 1.f / (float)max(dg, 1);
    float4 sf = reinterpret_cast<const float4*>(self)[(size_t)g * 16 + l];
    float4 bb = reinterpret_cast<const float4*>(bias)[l];
    float4 o;
    o.x = (a0.x + a1.x) * inv + sf.x + bb.x;
    o.y = (a0.y + a1.y) * inv + sf.y + bb.y;
    o.z = (a0.z + a1.z) * inv + sf.z + bb.z;
    o.w = (a0.w + a1.w) * inv + sf.w + bb.w;
    if (do_relu) {
        o.x = fmaxf(o.x, 0.f); o.y = fmaxf(o.y, 0.f);
        o.z = fmaxf(o.z, 0.f); o.w = fmaxf(o.w, 0.f);
    }
    reinterpret_cast<float4*>(out)[(size_t)g * 16 + l] = o;
}

// 16 lanes per supervision edge
__global__ void decode16_k(const float* __restrict__ u_c, const float* __restrict__ u_r,
                           const int* __restrict__ rows, const int* __restrict__ cols,
                           const float* __restrict__ b1, const float* __restrict__ w2,
                           const float* __restrict__ b2, float* __restrict__ out, int L) {
    int g = (blockIdx.x * blockDim.x + threadIdx.x) >> 4;
    int l = threadIdx.x & 15;
    if (g >= L) return;
    int r = __ldg(rows + g);
    int c = __ldg(cols + g);
    float4 a  = reinterpret_cast<const float4*>(u_c)[(size_t)r * 16 + l];
    float4 b  = reinterpret_cast<const float4*>(u_r)[(size_t)c * 16 + l];
    float4 bb = reinterpret_cast<const float4*>(b1)[l];
    float4 w  = reinterpret_cast<const float4*>(w2)[l];
    float h0 = fmaxf(a.x + b.x + bb.x, 0.f);
    float h1 = fmaxf(a.y + b.y + bb.y, 0.f);
    float h2 = fmaxf(a.z + b.z + bb.z, 0.f);
    float h3 = fmaxf(a.w + b.w + bb.w, 0.f);
    float s = (h0 * w.x + h1 * w.y) + (h2 * w.z + h3 * w.w);
#pragma unroll
    for (int off = 8; off; off >>= 1) s += __shfl_xor_sync(0xffffffffu, s, off);
    if (l == 0) out[g] = s + __ldg(b2);
}

// ---------------- launch ----------------

extern "C" void kernel_launch(void* const* d_in, const int* in_sizes, int n_in,
                              void* d_out, int out_size) {
    const float* x_c   = (const float*)d_in[0];
    const float* x_r   = (const float*)d_in[1];
    const float* W1crl = (const float*)d_in[2];
    const float* W1crr = (const float*)d_in[3];
    const float* b1cr  = (const float*)d_in[4];
    const float* W1rcl = (const float*)d_in[5];
    const float* W1rcr = (const float*)d_in[6];
    const float* b1rc  = (const float*)d_in[7];
    const float* W2crl = (const float*)d_in[8];
    const float* W2crr = (const float*)d_in[9];
    const float* b2cr  = (const float*)d_in[10];
    const float* W2rcl = (const float*)d_in[11];
    const float* W2rcr = (const float*)d_in[12];
    const float* b2rc  = (const float*)d_in[13];
    const float* Wd1   = (const float*)d_in[14];
    const float* bd1   = (const float*)d_in[15];
    const float* Wd2   = (const float*)d_in[16];
    const float* bd2   = (const float*)d_in[17];
    const int*   e_cr  = (const int*)d_in[18];
    const int*   e_rc  = (const int*)d_in[19];
    const int*   e_lab = (const int*)d_in[20];
    const int E_ = in_sizes[18] / 2;
    const int L_ = in_sizes[20] / 2;

    float *t_c, *t_r, *s_r, *s_c, *h_r, *h_c;
    float *wc_crl, *wc_crr, *wc_rcl, *wc_rcr, *bc_r, *bc_c;
    int *dg_r, *dg_c, *off_r, *off_c, *cur_r, *cur_c, *csr_cr, *csr_rc, *bsum;
    cudaGetSymbolAddress((void**)&t_c, g_t_c);
    cudaGetSymbolAddress((void**)&t_r, g_t_r);
    cudaGetSymbolAddress((void**)&s_r, g_s_r);
    cudaGetSymbolAddress((void**)&s_c, g_s_c);
    cudaGetSymbolAddress((void**)&h_r, g_h_r);
    cudaGetSymbolAddress((void**)&h_c, g_h_c);
    cudaGetSymbolAddress((void**)&dg_r, g_dg_r);
    cudaGetSymbolAddress((void**)&dg_c, g_dg_c);
    cudaGetSymbolAddress((void**)&off_r, g_off_r);
    cudaGetSymbolAddress((void**)&off_c, g_off_c);
    cudaGetSymbolAddress((void**)&cur_r, g_cur_r);
    cudaGetSymbolAddress((void**)&cur_c, g_cur_c);
    cudaGetSymbolAddress((void**)&csr_cr, g_csr_cr);
    cudaGetSymbolAddress((void**)&csr_rc, g_csr_rc);
    cudaGetSymbolAddress((void**)&bsum, g_bsum);
    cudaGetSymbolAddress((void**)&wc_crl, g_wc_crl);
    cudaGetSymbolAddress((void**)&wc_crr, g_wc_crr);
    cudaGetSymbolAddress((void**)&wc_rcl, g_wc_rcl);
    cudaGetSymbolAddress((void**)&wc_rcr, g_wc_rcr);
    cudaGetSymbolAddress((void**)&bc_r, g_bc_r);
    cudaGetSymbolAddress((void**)&bc_c, g_bc_c);

    // allow dynamic smem beyond 48KB for the K=128 tf32 GEMM (Whi+Wlo+X chunk)
    static int smem_set = 0;
    if (!smem_set) {
        cudaFuncSetAttribute(gemm_tf32_k, cudaFuncAttributeMaxDynamicSharedMemorySize,
                             (2 * 128 * HD + 2 * 32 * 32) * sizeof(float));
        smem_set = 1;
    }

    const int NT = 256;
    const int gE2   = (2 * E_ + NT - 1) / NT;
    const int gZ2   = (2 * (NCN / 4) + NT - 1) / NT;
    const int gN16  = (NCN * 16 + NT - 1) / NT;
    const int gL16  = (L_ * 16 + NT - 1) / NT;
    const int gG    = NCN / 32;   // 3125 (100000 % 32 == 0)
    const size_t smem64  = (size_t)(2 * 64  * HD + 2 * 32 * 32) * sizeof(float);
    const size_t smem128 = (size_t)(2 * 128 * HD + 2 * 32 * 32) * sizeof(float);

    const int* cr_s = e_cr;   const int* cr_d = e_cr + E_;
    const int* rc_s = e_rc;   const int* rc_d = e_rc + E_;
    const int* lb_r = e_lab;  const int* lb_c = e_lab + L_;

    const float* Wd_top = Wd1;
    const float* Wd_bot = Wd1 + HD * HD;

    // ---- decoder fold ----
    fold_k<<<258, HD>>>(W2crl, W2crr, W2rcl, W2rcr, b2cr, b2rc, Wd_top, Wd_bot,
                        wc_crl, wc_crr, wc_rcl, wc_rcr, bc_r, bc_c);

    // ---- degrees ----
    zero2_k<<<gZ2, NT>>>((int4*)dg_r, (int4*)dg_c, NRN / 4);
    degree2_k<<<gE2, NT>>>(cr_d, dg_r, rc_d, dg_c, E_);

    // ---- CSR build ----
    scan_block2_k<<<2 * NSCANB, SCAN_BS>>>(dg_r, off_r, dg_c, off_c, bsum, NCN);
    scan_sums2_k<<<2, 1024>>>(bsum);
    scan_add_copy2_k<<<2 * NSCANB, SCAN_BS>>>(off_r, cur_r, off_c, cur_c, bsum, NCN);
    csr_fill2_k<<<gE2, NT>>>(cr_s, cr_d, cur_r, csr_cr, rc_s, rc_d, cur_c, csr_rc, E_);

    // ---- layer 1 transforms (tensor-core 3xTF32, v2) ----
    gemm_tf32_k<<<gG, NT, smem128>>>(x_c, W1crl, t_c, 128);
    gemm_tf32_k<<<gG, NT, smem64 >>>(x_r, W1crr, s_r, 64);
    gemm_tf32_k<<<gG, NT, smem64 >>>(x_r, W1rcl, t_r, 64);
    gemm_tf32_k<<<gG, NT, smem128>>>(x_c, W1rcr, s_c, 128);

    // ---- layer 1 aggregate (relu) ----
    aggregate16_k<<<gN16, NT>>>(t_c, s_r, b1cr, off_r, dg_r, csr_cr, h_r, NRN, 1);
    aggregate16_k<<<gN16, NT>>>(t_r, s_c, b1rc, off_c, dg_c, csr_rc, h_c, NCN, 1);

    // ---- layer 2 transforms (tensor-core, decoder-space) ----
    gemm_tf32_k<<<gG, NT, smem64>>>(h_c, wc_crl, t_c, 64);
    gemm_tf32_k<<<gG, NT, smem64>>>(h_r, wc_crr, s_r, 64);
    gemm_tf32_k<<<gG, NT, smem64>>>(h_r, wc_rcl, t_r, 64);
    gemm_tf32_k<<<gG, NT, smem64>>>(h_c, wc_rcr, s_c, 64);

    // ---- layer 2 aggregate -> u_r (h_r), u_c (h_c) ----
    aggregate16_k<<<gN16, NT>>>(t_c, s_r, bc_r, off_r, dg_r, csr_cr, h_r, NRN, 0);
    aggregate16_k<<<gN16, NT>>>(t_r, s_c, bc_c, off_c, dg_c, csr_rc, h_c, NCN, 0);

    // ---- decode ----
    decode16_k<<<gL16, NT>>>(h_c, h_r, lb_r, lb_c, bd1, Wd2, bd2, (float*)d_out, L_);
}

// round 10
// speedup vs baseline: 1.4252x; 1.4252x over previous
#include <cuda_runtime.h>
#include <cuda_bf16.h>
#include <stdint.h>

#define NCN 100000
#define NRN 100000
#define HD  64
#define EMAX 2000000
#define SCAN_BS 256
#define NSCANB 391   // ceil(100000/256)

// ---------------- scratch (device globals: allocation-free) ----------------
__device__ float g_t_c[(size_t)NCN * HD];
__device__ float g_t_r[(size_t)NRN * HD];
__device__ float g_s_r[(size_t)NRN * HD];
__device__ float g_s_c[(size_t)NCN * HD];
__device__ float g_h_r[(size_t)NRN * HD];
__device__ float g_h_c[(size_t)NCN * HD];
__device__ int   g_dg_r[NRN];
__device__ int   g_dg_c[NCN];
__device__ int   g_off_r[NRN];
__device__ int   g_off_c[NCN];
__device__ int   g_cur_r[NRN];
__device__ int   g_cur_c[NCN];
__device__ int   g_csr_cr[EMAX];   // pre-scaled src*16 (float4 index)
__device__ int   g_csr_rc[EMAX];
__device__ int   g_bsum[2 * NSCANB + 2];
// folded decoder weights/biases
__device__ float g_wc_crl[HD * HD];
__device__ float g_wc_crr[HD * HD];
__device__ float g_wc_rcl[HD * HD];
__device__ float g_wc_rcr[HD * HD];
__device__ float g_bc_r[HD];
__device__ float g_bc_c[HD];

// ---------------- kernels ----------------

__global__ void zero2_k(int4* __restrict__ a, int4* __restrict__ b, int n4) {
    int i = blockIdx.x * blockDim.x + threadIdx.x;
    if (i < n4) a[i] = make_int4(0, 0, 0, 0);
    else if (i < 2 * n4) b[i - n4] = make_int4(0, 0, 0, 0);
}

__global__ void degree2_k(const int* __restrict__ dstA, int* __restrict__ degA,
                          const int* __restrict__ dstB, int* __restrict__ degB, int nE) {
    int i = blockIdx.x * blockDim.x + threadIdx.x;
    if (i < nE) atomicAdd(degA + __ldg(dstA + i), 1);
    else if (i < 2 * nE) atomicAdd(degB + __ldg(dstB + (i - nE)), 1);
}

// --- segmented 3-kernel exclusive scan: segment 0 = relation A, 1 = relation B ---
__global__ void scan_block2_k(const int* __restrict__ inA, int* __restrict__ outA,
                              const int* __restrict__ inB, int* __restrict__ outB,
                              int* __restrict__ bsum, int n) {
    __shared__ int sh[SCAN_BS];
    int b = blockIdx.x;
    const int* in;
    int* out;
    int lb;
    if (b < NSCANB) { in = inA; out = outA; lb = b; }
    else            { in = inB; out = outB; lb = b - NSCANB; }
    int i = lb * SCAN_BS + threadIdx.x;
    int v = (i < n) ? in[i] : 0;
    sh[threadIdx.x] = v;
    __syncthreads();
    for (int off = 1; off < SCAN_BS; off <<= 1) {
        int t = (threadIdx.x >= off) ? sh[threadIdx.x - off] : 0;
        __syncthreads();
        sh[threadIdx.x] += t;
        __syncthreads();
    }
    if (i < n) out[i] = sh[threadIdx.x] - v;
    if (threadIdx.x == SCAN_BS - 1) bsum[b] = sh[threadIdx.x];
}

__global__ void scan_sums2_k(int* __restrict__ bsum) {
    __shared__ int sh[1024];
    int* seg = bsum + blockIdx.x * NSCANB;
    int v = (threadIdx.x < NSCANB) ? seg[threadIdx.x] : 0;
    sh[threadIdx.x] = v;
    __syncthreads();
    for (int off = 1; off < 1024; off <<= 1) {
        int t = (threadIdx.x >= off) ? sh[threadIdx.x - off] : 0;
        __syncthreads();
        sh[threadIdx.x] += t;
        __syncthreads();
    }
    if (threadIdx.x < NSCANB) seg[threadIdx.x] = sh[threadIdx.x] - v;
}

__global__ void scan_add_copy2_k(int* __restrict__ outA, int* __restrict__ curA,
                                 int* __restrict__ outB, int* __restrict__ curB,
                                 const int* __restrict__ bsum, int n) {
    int b = blockIdx.x;
    int* out;
    int* cur;
    int lb;
    if (b < NSCANB) { out = outA; cur = curA; lb = b; }
    else            { out = outB; cur = curB; lb = b - NSCANB; }
    int i = lb * SCAN_BS + threadIdx.x;
    if (i < n) {
        int v = out[i] + bsum[b];
        out[i] = v;
        cur[i] = v;
    }
}

// both relations' CSR fill; stores src*16 (float4 row base index)
__global__ void csr_fill2_k(const int* __restrict__ srcA, const int* __restrict__ dstA,
                            int* __restrict__ curA, int* __restrict__ csrA,
                            const int* __restrict__ srcB, const int* __restrict__ dstB,
                            int* __restrict__ curB, int* __restrict__ csrB, int nE) {
    int i = blockIdx.x * blockDim.x + threadIdx.x;
    if (i < nE) {
        int d = __ldg(dstA + i);
        int p = atomicAdd(curA + d, 1);
        csrA[p] = __ldg(srcA + i) << 4;
    } else if (i < 2 * nE) {
        int j = i - nE;
        int d = __ldg(dstB + j);
        int p = atomicAdd(curB + d, 1);
        csrB[p] = __ldg(srcB + j) << 4;
    }
}

// One launch for the whole decoder fold (258 blocks of 64 threads).
__global__ void fold_k(const float* __restrict__ W2crl, const float* __restrict__ W2crr,
                       const float* __restrict__ W2rcl, const float* __restrict__ W2rcr,
                       const float* __restrict__ b2cr,  const float* __restrict__ b2rc,
                       const float* __restrict__ Wd_top, const float* __restrict__ Wd_bot,
                       float* __restrict__ wc_crl, float* __restrict__ wc_crr,
                       float* __restrict__ wc_rcl, float* __restrict__ wc_rcr,
                       float* __restrict__ bc_r, float* __restrict__ bc_c) {
    __shared__ float Ar[HD];
    int b = blockIdx.x, j = threadIdx.x;
    const float *Arow, *B;
    float* Crow;
    if (b < 256) {
        int which = b >> 6, r = b & 63;
        switch (which) {
            case 0: Arow = W2crl + r * HD; B = Wd_bot; Crow = wc_crl + r * HD; break;
            case 1: Arow = W2crr + r * HD; B = Wd_bot; Crow = wc_crr + r * HD; break;
            case 2: Arow = W2rcl + r * HD; B = Wd_top; Crow = wc_rcl + r * HD; break;
            default:Arow = W2rcr + r * HD; B = Wd_top; Crow = wc_rcr + r * HD; break;
        }
    } else if (b == 256) { Arow = b2cr; B = Wd_bot; Crow = bc_r; }
    else                 { Arow = b2rc; B = Wd_top; Crow = bc_c; }
    Ar[j] = Arow[j];
    __syncthreads();
    float s = 0.f;
#pragma unroll 16
    for (int k = 0; k < HD; k++) s += Ar[k] * B[k * HD + j];
    Crow[j] = s;
}

// Y[n,64] = X[n,K] @ W[K,64].  W cached in shared; one thread per row. (R2/R6-proven)
__global__ void gemm_nk(const float* __restrict__ X, const float* __restrict__ W,
                        float* __restrict__ Y, int n, int K) {
    extern __shared__ float Ws[]; // K*64
    for (int i = threadIdx.x; i < K * HD; i += blockDim.x) Ws[i] = W[i];
    __syncthreads();
    int row = blockIdx.x * blockDim.x + threadIdx.x;
    if (row >= n) return;
    float acc[HD];
#pragma unroll
    for (int j = 0; j < HD; j++) acc[j] = 0.f;
    const float* xr = X + (size_t)row * K;
    for (int k = 0; k < K; k += 4) {
        float4 xv = *reinterpret_cast<const float4*>(xr + k);
        float xs[4] = {xv.x, xv.y, xv.z, xv.w};
#pragma unroll
        for (int kk = 0; kk < 4; kk++) {
            const float4* wrow = reinterpret_cast<const float4*>(Ws + (k + kk) * HD);
            float x = xs[kk];
#pragma unroll
            for (int j4 = 0; j4 < HD / 4; j4++) {
                float4 w = wrow[j4];
                acc[j4 * 4 + 0] += x * w.x;
                acc[j4 * 4 + 1] += x * w.y;
                acc[j4 * 4 + 2] += x * w.z;
                acc[j4 * 4 + 3] += x * w.w;
            }
        }
    }
    float4* yr = reinterpret_cast<float4*>(Y + (size_t)row * HD);
#pragma unroll
    for (int j4 = 0; j4 < HD / 4; j4++)
        yr[j4] = make_float4(acc[j4 * 4], acc[j4 * 4 + 1], acc[j4 * 4 + 2], acc[j4 * 4 + 3]);
}

// Fused gather-aggregate + mean + self + bias (+relu).
// 16 lanes per dst node (float4 per lane); csr holds pre-scaled src*16; unroll-4.
__global__ void aggregate16_k(const float* __restrict__ feat, const float* __restrict__ self,
                              const float* __restrict__ bias, const int* __restrict__ offs,
                              const int* __restrict__ deg, const int* __restrict__ csr,
                              float* __restrict__ out, int n, int do_relu) {
    int g = (blockIdx.x * blockDim.x + threadIdx.x) >> 4;
    int l = threadIdx.x & 15;
    if (g >= n) return;
    int beg = __ldg(offs + g);
    int dg  = __ldg(deg + g);
    int end = beg + dg;
    const float4* feat4 = reinterpret_cast<const float4*>(feat);
    float4 a0 = make_float4(0.f, 0.f, 0.f, 0.f);
    float4 a1 = make_float4(0.f, 0.f, 0.f, 0.f);
    float4 a2 = make_float4(0.f, 0.f, 0.f, 0.f);
    float4 a3 = make_float4(0.f, 0.f, 0.f, 0.f);
    int e = beg;
    for (; e + 3 < end; e += 4) {
        int s0 = __ldg(csr + e);
        int s1 = __ldg(csr + e + 1);
        int s2 = __ldg(csr + e + 2);
        int s3 = __ldg(csr + e + 3);
        float4 v0 = feat4[s0 + l];
        float4 v1 = feat4[s1 + l];
        float4 v2 = feat4[s2 + l];
        float4 v3 = feat4[s3 + l];
        a0.x += v0.x; a0.y += v0.y; a0.z += v0.z; a0.w += v0.w;
        a1.x += v1.x; a1.y += v1.y; a1.z += v1.z; a1.w += v1.w;
        a2.x += v2.x; a2.y += v2.y; a2.z += v2.z; a2.w += v2.w;
        a3.x += v3.x; a3.y += v3.y; a3.z += v3.z; a3.w += v3.w;
    }
    for (; e < end; e++) {
        int s0 = __ldg(csr + e);
        float4 v0 = feat4[s0 + l];
        a0.x += v0.x; a0.y += v0.y; a0.z += v0.z; a0.w += v0.w;
    }
    a0.x += a1.x; a0.y += a1.y; a0.z += a1.z; a0.w += a1.w;
    a2.x += a3.x; a2.y += a3.y; a2.z += a3.z; a2.w += a3.w;
    float inv = 1.f / (float)max(dg, 1);
    float4 sf = reinterpret_cast<const float4*>(self)[(size_t)g * 16 + l];
    float4 bb = reinterpret_cast<const float4*>(bias)[l];
    float4 o;
    o.x = (a0.x + a2.x) * inv + sf.x + bb.x;
    o.y = (a0.y + a2.y) * inv + sf.y + bb.y;
    o.z = (a0.z + a2.z) * inv + sf.z + bb.z;
    o.w = (a0.w + a2.w) * inv + sf.w + bb.w;
    if (do_relu) {
        o.x = fmaxf(o.x, 0.f); o.y = fmaxf(o.y, 0.f);
        o.z = fmaxf(o.z, 0.f); o.w = fmaxf(o.w, 0.f);
    }
    reinterpret_cast<float4*>(out)[(size_t)g * 16 + l] = o;
}

// 16 lanes per supervision edge
__global__ void decode16_k(const float* __restrict__ u_c, const float* __restrict__ u_r,
                           const int* __restrict__ rows, const int* __restrict__ cols,
                           const float* __restrict__ b1, const float* __restrict__ w2,
                           const float* __restrict__ b2, float* __restrict__ out, int L) {
    int g = (blockIdx.x * blockDim.x + threadIdx.x) >> 4;
    int l = threadIdx.x & 15;
    if (g >= L) return;
    int r = __ldg(rows + g);
    int c = __ldg(cols + g);
    float4 a  = reinterpret_cast<const float4*>(u_c)[(size_t)r * 16 + l];
    float4 b  = reinterpret_cast<const float4*>(u_r)[(size_t)c * 16 + l];
    float4 bb = reinterpret_cast<const float4*>(b1)[l];
    float4 w  = reinterpret_cast<const float4*>(w2)[l];
    float h0 = fmaxf(a.x + b.x + bb.x, 0.f);
    float h1 = fmaxf(a.y + b.y + bb.y, 0.f);
    float h2 = fmaxf(a.z + b.z + bb.z, 0.f);
    float h3 = fmaxf(a.w + b.w + bb.w, 0.f);
    float s = (h0 * w.x + h1 * w.y) + (h2 * w.z + h3 * w.w);
#pragma unroll
    for (int off = 8; off; off >>= 1) s += __shfl_xor_sync(0xffffffffu, s, off);
    if (l == 0) out[g] = s + __ldg(b2);
}

// ---------------- launch ----------------

extern "C" void kernel_launch(void* const* d_in, const int* in_sizes, int n_in,
                              void* d_out, int out_size) {
    const float* x_c   = (const float*)d_in[0];
    const float* x_r   = (const float*)d_in[1];
    const float* W1crl = (const float*)d_in[2];
    const float* W1crr = (const float*)d_in[3];
    const float* b1cr  = (const float*)d_in[4];
    const float* W1rcl = (const float*)d_in[5];
    const float* W1rcr = (const float*)d_in[6];
    const float* b1rc  = (const float*)d_in[7];
    const float* W2crl = (const float*)d_in[8];
    const float* W2crr = (const float*)d_in[9];
    const float* b2cr  = (const float*)d_in[10];
    const float* W2rcl = (const float*)d_in[11];
    const float* W2rcr = (const float*)d_in[12];
    const float* b2rc  = (const float*)d_in[13];
    const float* Wd1   = (const float*)d_in[14];
    const float* bd1   = (const float*)d_in[15];
    const float* Wd2   = (const float*)d_in[16];
    const float* bd2   = (const float*)d_in[17];
    const int*   e_cr  = (const int*)d_in[18];
    const int*   e_rc  = (const int*)d_in[19];
    const int*   e_lab = (const int*)d_in[20];
    const int E_ = in_sizes[18] / 2;
    const int L_ = in_sizes[20] / 2;

    float *t_c, *t_r, *s_r, *s_c, *h_r, *h_c;
    float *wc_crl, *wc_crr, *wc_rcl, *wc_rcr, *bc_r, *bc_c;
    int *dg_r, *dg_c, *off_r, *off_c, *cur_r, *cur_c, *csr_cr, *csr_rc, *bsum;
    cudaGetSymbolAddress((void**)&t_c, g_t_c);
    cudaGetSymbolAddress((void**)&t_r, g_t_r);
    cudaGetSymbolAddress((void**)&s_r, g_s_r);
    cudaGetSymbolAddress((void**)&s_c, g_s_c);
    cudaGetSymbolAddress((void**)&h_r, g_h_r);
    cudaGetSymbolAddress((void**)&h_c, g_h_c);
    cudaGetSymbolAddress((void**)&dg_r, g_dg_r);
    cudaGetSymbolAddress((void**)&dg_c, g_dg_c);
    cudaGetSymbolAddress((void**)&off_r, g_off_r);
    cudaGetSymbolAddress((void**)&off_c, g_off_c);
    cudaGetSymbolAddress((void**)&cur_r, g_cur_r);
    cudaGetSymbolAddress((void**)&cur_c, g_cur_c);
    cudaGetSymbolAddress((void**)&csr_cr, g_csr_cr);
    cudaGetSymbolAddress((void**)&csr_rc, g_csr_rc);
    cudaGetSymbolAddress((void**)&bsum, g_bsum);
    cudaGetSymbolAddress((void**)&wc_crl, g_wc_crl);
    cudaGetSymbolAddress((void**)&wc_crr, g_wc_crr);
    cudaGetSymbolAddress((void**)&wc_rcl, g_wc_rcl);
    cudaGetSymbolAddress((void**)&wc_rcr, g_wc_rcr);
    cudaGetSymbolAddress((void**)&bc_r, g_bc_r);
    cudaGetSymbolAddress((void**)&bc_c, g_bc_c);

    const int NT = 256;
    const int gRow  = (NCN + NT - 1) / NT;
    const int gE2   = (2 * E_ + NT - 1) / NT;
    const int gZ2   = (2 * (NCN / 4) + NT - 1) / NT;
    const int gN16  = (NCN * 16 + NT - 1) / NT;
    const int gL16  = (L_ * 16 + NT - 1) / NT;

    const int* cr_s = e_cr;   const int* cr_d = e_cr + E_;
    const int* rc_s = e_rc;   const int* rc_d = e_rc + E_;
    const int* lb_r = e_lab;  const int* lb_c = e_lab + L_;

    const float* Wd_top = Wd1;
    const float* Wd_bot = Wd1 + HD * HD;

    // ---- decoder fold ----
    fold_k<<<258, HD>>>(W2crl, W2crr, W2rcl, W2rcr, b2cr, b2rc, Wd_top, Wd_bot,
                        wc_crl, wc_crr, wc_rcl, wc_rcr, bc_r, bc_c);

    // ---- degrees ----
    zero2_k<<<gZ2, NT>>>((int4*)dg_r, (int4*)dg_c, NRN / 4);
    degree2_k<<<gE2, NT>>>(cr_d, dg_r, rc_d, dg_c, E_);

    // ---- CSR build ----
    scan_block2_k<<<2 * NSCANB, SCAN_BS>>>(dg_r, off_r, dg_c, off_c, bsum, NCN);
    scan_sums2_k<<<2, 1024>>>(bsum);
    scan_add_copy2_k<<<2 * NSCANB, SCAN_BS>>>(off_r, cur_r, off_c, cur_c, bsum, NCN);
    csr_fill2_k<<<gE2, NT>>>(cr_s, cr_d, cur_r, csr_cr, rc_s, rc_d, cur_c, csr_rc, E_);

    // ---- layer 1 transforms (scalar FFMA, separate launches — R6-proven) ----
    gemm_nk<<<gRow, NT, 128 * HD * sizeof(float)>>>(x_c, W1crl, t_c, NCN, 128);
    gemm_nk<<<gRow, NT,  64 * HD * sizeof(float)>>>(x_r, W1crr, s_r, NRN, 64);
    gemm_nk<<<gRow, NT,  64 * HD * sizeof(float)>>>(x_r, W1rcl, t_r, NRN, 64);
    gemm_nk<<<gRow, NT, 128 * HD * sizeof(float)>>>(x_c, W1rcr, s_c, NCN, 128);

    // ---- layer 1 aggregate (relu) ----
    aggregate16_k<<<gN16, NT>>>(t_c, s_r, b1cr, off_r, dg_r, csr_cr, h_r, NRN, 1);
    aggregate16_k<<<gN16, NT>>>(t_r, s_c, b1rc, off_c, dg_c, csr_rc, h_c, NCN, 1);

    // ---- layer 2 transforms (decoder-space) ----
    gemm_nk<<<gRow, NT, 64 * HD * sizeof(float)>>>(h_c, wc_crl, t_c, NCN, 64);
    gemm_nk<<<gRow, NT, 64 * HD * sizeof(float)>>>(h_r, wc_crr, s_r, NRN, 64);
    gemm_nk<<<gRow, NT, 64 * HD * sizeof(float)>>>(h_r, wc_rcl, t_r, NRN, 64);
    gemm_nk<<<gRow, NT, 64 * HD * sizeof(float)>>>(h_c, wc_rcr, s_c, NCN, 64);

    // ---- layer 2 aggregate -> u_r (h_r), u_c (h_c) ----
    aggregate16_k<<<gN16, NT>>>(t_c, s_r, bc_r, off_r, dg_r, csr_cr, h_r, NRN, 0);
    aggregate16_k<<<gN16, NT>>>(t_r, s_c, bc_c, off_c, dg_c, csr_rc, h_c, NCN, 0);

    // ---- decode ----
    decode16_k<<<gL16, NT>>>(h_c, h_r, lb_r, lb_c, bd1, Wd2, bd2, (float*)d_out, L_);
}

// round 12
// speedup vs baseline: 1.5986x; 1.1216x over previous
#include <cuda_runtime.h>
#include <cuda_fp16.h>
#include <stdint.h>

#define NCN 100000
#define NRN 100000
#define HD  64
#define EMAX 2000000
#define SCAN_BS 256
#define NSCANB 391   // ceil(100000/256)

// ---------------- scratch (device globals: allocation-free) ----------------
// fp16 message buffers stored as uint4 rows (8 uint4 = 64 halves per row) -> 16B aligned
__device__ uint4  g_t_c4[(size_t)NCN * HD / 8];
__device__ uint4  g_t_r4[(size_t)NRN * HD / 8];
__device__ float  g_s_r[(size_t)NRN * HD];   // self terms (linear access, fp32)
__device__ float  g_s_c[(size_t)NCN * HD];
__device__ float  g_h_r[(size_t)NRN * HD];
__device__ float  g_h_c[(size_t)NCN * HD];
__device__ int    g_dg_r[NRN];
__device__ int    g_dg_c[NCN];
__device__ int    g_off_r[NRN];
__device__ int    g_off_c[NCN];
__device__ int    g_cur_r[NRN];
__device__ int    g_cur_c[NCN];
__device__ int    g_csr_cr[EMAX];
__device__ int    g_csr_rc[EMAX];
__device__ int    g_bsum[2 * NSCANB + 2];
// folded decoder weights/biases
__device__ float  g_wc_crl[HD * HD];
__device__ float  g_wc_crr[HD * HD];
__device__ float  g_wc_rcl[HD * HD];
__device__ float  g_wc_rcr[HD * HD];
__device__ float  g_bc_r[HD];
__device__ float  g_bc_c[HD];

// ---- well-defined fp16 bit packing helpers (no punning) ----
__device__ __forceinline__ unsigned pack_h2(float a, float b) {
    unsigned lo = (unsigned)__half_as_ushort(__float2half_rn(a));
    unsigned hi = (unsigned)__half_as_ushort(__float2half_rn(b));
    return lo | (hi << 16);
}
__device__ __forceinline__ float2 unpack_h2(unsigned w) {
    __half2 h = __halves2half2(__ushort_as_half((unsigned short)(w & 0xFFFFu)),
                               __ushort_as_half((unsigned short)(w >> 16)));
    return __half22float2(h);
}

// ---------------- kernels ----------------

__global__ void zero2_k(int4* __restrict__ a, int4* __restrict__ b, int n4) {
    int i = blockIdx.x * blockDim.x + threadIdx.x;
    if (i < n4) a[i] = make_int4(0, 0, 0, 0);
    else if (i < 2 * n4) b[i - n4] = make_int4(0, 0, 0, 0);
}

__global__ void degree2_k(const int* __restrict__ dstA, int* __restrict__ degA,
                          const int* __restrict__ dstB, int* __restrict__ degB, int nE) {
    int i = blockIdx.x * blockDim.x + threadIdx.x;
    if (i < nE) atomicAdd(degA + __ldg(dstA + i), 1);
    else if (i < 2 * nE) atomicAdd(degB + __ldg(dstB + (i - nE)), 1);
}

// --- segmented 3-kernel exclusive scan: segment 0 = relation A, 1 = relation B ---
__global__ void scan_block2_k(const int* __restrict__ inA, int* __restrict__ outA,
                              const int* __restrict__ inB, int* __restrict__ outB,
                              int* __restrict__ bsum, int n) {
    __shared__ int sh[SCAN_BS];
    int b = blockIdx.x;
    const int* in;
    int* out;
    int lb;
    if (b < NSCANB) { in = inA; out = outA; lb = b; }
    else            { in = inB; out = outB; lb = b - NSCANB; }
    int i = lb * SCAN_BS + threadIdx.x;
    int v = (i < n) ? in[i] : 0;
    sh[threadIdx.x] = v;
    __syncthreads();
    for (int off = 1; off < SCAN_BS; off <<= 1) {
        int t = (threadIdx.x >= off) ? sh[threadIdx.x - off] : 0;
        __syncthreads();
        sh[threadIdx.x] += t;
        __syncthreads();
    }
    if (i < n) out[i] = sh[threadIdx.x] - v;
    if (threadIdx.x == SCAN_BS - 1) bsum[b] = sh[threadIdx.x];
}

__global__ void scan_sums2_k(int* __restrict__ bsum) {
    __shared__ int sh[1024];
    int* seg = bsum + blockIdx.x * NSCANB;
    int v = (threadIdx.x < NSCANB) ? seg[threadIdx.x] : 0;
    sh[threadIdx.x] = v;
    __syncthreads();
    for (int off = 1; off < 1024; off <<= 1) {
        int t = (threadIdx.x >= off) ? sh[threadIdx.x - off] : 0;
        __syncthreads();
        sh[threadIdx.x] += t;
        __syncthreads();
    }
    if (threadIdx.x < NSCANB) seg[threadIdx.x] = sh[threadIdx.x] - v;
}

__global__ void scan_add_copy2_k(int* __restrict__ outA, int* __restrict__ curA,
                                 int* __restrict__ outB, int* __restrict__ curB,
                                 const int* __restrict__ bsum, int n) {
    int b = blockIdx.x;
    int* out;
    int* cur;
    int lb;
    if (b < NSCANB) { out = outA; cur = curA; lb = b; }
    else            { out = outB; cur = curB; lb = b - NSCANB; }
    int i = lb * SCAN_BS + threadIdx.x;
    if (i < n) {
        int v = out[i] + bsum[b];
        out[i] = v;
        cur[i] = v;
    }
}

// both relations' CSR fill (plain src ids)
__global__ void csr_fill2_k(const int* __restrict__ srcA, const int* __restrict__ dstA,
                            int* __restrict__ curA, int* __restrict__ csrA,
                            const int* __restrict__ srcB, const int* __restrict__ dstB,
                            int* __restrict__ curB, int* __restrict__ csrB, int nE) {
    int i = blockIdx.x * blockDim.x + threadIdx.x;
    if (i < nE) {
        int d = __ldg(dstA + i);
        int p = atomicAdd(curA + d, 1);
        csrA[p] = __ldg(srcA + i);
    } else if (i < 2 * nE) {
        int j = i - nE;
        int d = __ldg(dstB + j);
        int p = atomicAdd(curB + d, 1);
        csrB[p] = __ldg(srcB + j);
    }
}

// One launch for the whole decoder fold (258 blocks of 64 threads).
__global__ void fold_k(const float* __restrict__ W2crl, const float* __restrict__ W2crr,
                       const float* __restrict__ W2rcl, const float* __restrict__ W2rcr,
                       const float* __restrict__ b2cr,  const float* __restrict__ b2rc,
                       const float* __restrict__ Wd_top, const float* __restrict__ Wd_bot,
                       float* __restrict__ wc_crl, float* __restrict__ wc_crr,
                       float* __restrict__ wc_rcl, float* __restrict__ wc_rcr,
                       float* __restrict__ bc_r, float* __restrict__ bc_c) {
    __shared__ float Ar[HD];
    int b = blockIdx.x, j = threadIdx.x;
    const float *Arow, *B;
    float* Crow;
    if (b < 256) {
        int which = b >> 6, r = b & 63;
        switch (which) {
            case 0: Arow = W2crl + r * HD; B = Wd_bot; Crow = wc_crl + r * HD; break;
            case 1: Arow = W2crr + r * HD; B = Wd_bot; Crow = wc_crr + r * HD; break;
            case 2: Arow = W2rcl + r * HD; B = Wd_top; Crow = wc_rcl + r * HD; break;
            default:Arow = W2rcr + r * HD; B = Wd_top; Crow = wc_rcr + r * HD; break;
        }
    } else if (b == 256) { Arow = b2cr; B = Wd_bot; Crow = bc_r; }
    else                 { Arow = b2rc; B = Wd_top; Crow = bc_c; }
    Ar[j] = Arow[j];
    __syncthreads();
    float s = 0.f;
#pragma unroll 16
    for (int k = 0; k < HD; k++) s += Ar[k] * B[k * HD + j];
    Crow[j] = s;
}

// Y[n,64] = X[n,K] @ W[K,64], fp32 output.  W cached in shared; one thread per row.
__global__ void gemm_nk(const float* __restrict__ X, const float* __restrict__ W,
                        float* __restrict__ Y, int n, int K) {
    extern __shared__ float Ws[]; // K*64
    for (int i = threadIdx.x; i < K * HD; i += blockDim.x) Ws[i] = W[i];
    __syncthreads();
    int row = blockIdx.x * blockDim.x + threadIdx.x;
    if (row >= n) return;
    float acc[HD];
#pragma unroll
    for (int j = 0; j < HD; j++) acc[j] = 0.f;
    const float* xr = X + (size_t)row * K;
    for (int k = 0; k < K; k += 4) {
        float4 xv = *reinterpret_cast<const float4*>(xr + k);
        float xs[4] = {xv.x, xv.y, xv.z, xv.w};
#pragma unroll
        for (int kk = 0; kk < 4; kk++) {
            const float4* wrow = reinterpret_cast<const float4*>(Ws + (k + kk) * HD);
            float x = xs[kk];
#pragma unroll
            for (int j4 = 0; j4 < HD / 4; j4++) {
                float4 w = wrow[j4];
                acc[j4 * 4 + 0] += x * w.x;
                acc[j4 * 4 + 1] += x * w.y;
                acc[j4 * 4 + 2] += x * w.z;
                acc[j4 * 4 + 3] += x * w.w;
            }
        }
    }
    float4* yr = reinterpret_cast<float4*>(Y + (size_t)row * HD);
#pragma unroll
    for (int j4 = 0; j4 < HD / 4; j4++)
        yr[j4] = make_float4(acc[j4 * 4], acc[j4 * 4 + 1], acc[j4 * 4 + 2], acc[j4 * 4 + 3]);
}

// Same GEMM but fp16-packed output rows (8 uint4 per row), well-defined packing.
__global__ void gemm_nk_h(const float* __restrict__ X, const float* __restrict__ W,
                          uint4* __restrict__ Y4, int n, int K) {
    extern __shared__ float Ws[]; // K*64
    for (int i = threadIdx.x; i < K * HD; i += blockDim.x) Ws[i] = W[i];
    __syncthreads();
    int row = blockIdx.x * blockDim.x + threadIdx.x;
    if (row >= n) return;
    float acc[HD];
#pragma unroll
    for (int j = 0; j < HD; j++) acc[j] = 0.f;
    const float* xr = X + (size_t)row * K;
    for (int k = 0; k < K; k += 4) {
        float4 xv = *reinterpret_cast<const float4*>(xr + k);
        float xs[4] = {xv.x, xv.y, xv.z, xv.w};
#pragma unroll
        for (int kk = 0; kk < 4; kk++) {
            const float4* wrow = reinterpret_cast<const float4*>(Ws + (k + kk) * HD);
            float x = xs[kk];
#pragma unroll
            for (int j4 = 0; j4 < HD / 4; j4++) {
                float4 w = wrow[j4];
                acc[j4 * 4 + 0] += x * w.x;
                acc[j4 * 4 + 1] += x * w.y;
                acc[j4 * 4 + 2] += x * w.z;
                acc[j4 * 4 + 3] += x * w.w;
            }
        }
    }
    uint4* yr = Y4 + (size_t)row * 8;   // 8 uint4 per 64-half row
#pragma unroll
    for (int p = 0; p < 8; p++) {
        uint4 v;
        v.x = pack_h2(acc[8 * p + 0], acc[8 * p + 1]);
        v.y = pack_h2(acc[8 * p + 2], acc[8 * p + 3]);
        v.z = pack_h2(acc[8 * p + 4], acc[8 * p + 5]);
        v.w = pack_h2(acc[8 * p + 6], acc[8 * p + 7]);
        yr[p] = v;
    }
}

// Fused gather-aggregate + mean + self + bias (+relu).
// 16 lanes per dst node; fp16 messages: each lane loads 8B (uint2 = 4 halves) ->
// one 128B line per edge. fp32 accumulation. unroll-2 (R6-proven MLP).
__global__ void aggregate16_k(const uint2* __restrict__ feat2, const float* __restrict__ self,
                              const float* __restrict__ bias, const int* __restrict__ offs,
                              const int* __restrict__ deg, const int* __restrict__ csr,
                              float* __restrict__ out, int n, int do_relu) {
    int g = (blockIdx.x * blockDim.x + threadIdx.x) >> 4;
    int l = threadIdx.x & 15;
    if (g >= n) return;
    int beg = __ldg(offs + g);
    int dg  = __ldg(deg + g);
    int end = beg + dg;
    float4 a0 = make_float4(0.f, 0.f, 0.f, 0.f);
    float4 a1 = make_float4(0.f, 0.f, 0.f, 0.f);
    int e = beg;
    for (; e + 1 < end; e += 2) {
        int s0 = __ldg(csr + e);
        int s1 = __ldg(csr + e + 1);
        uint2 v0 = __ldg(feat2 + (size_t)s0 * 16 + l);   // 16 uint2 per row
        uint2 v1 = __ldg(feat2 + (size_t)s1 * 16 + l);
        float2 f00 = unpack_h2(v0.x);
        float2 f01 = unpack_h2(v0.y);
        float2 f10 = unpack_h2(v1.x);
        float2 f11 = unpack_h2(v1.y);
        a0.x += f00.x; a0.y += f00.y; a0.z += f01.x; a0.w += f01.y;
        a1.x += f10.x; a1.y += f10.y; a1.z += f11.x; a1.w += f11.y;
    }
    if (e < end) {
        int s0 = __ldg(csr + e);
        uint2 v0 = __ldg(feat2 + (size_t)s0 * 16 + l);
        float2 f00 = unpack_h2(v0.x);
        float2 f01 = unpack_h2(v0.y);
        a0.x += f00.x; a0.y += f00.y; a0.z += f01.x; a0.w += f01.y;
    }
    float inv = 1.f / (float)max(dg, 1);
    float4 sf = reinterpret_cast<const float4*>(self)[(size_t)g * 16 + l];
    float4 bb = reinterpret_cast<const float4*>(bias)[l];
    float4 o;
    o.x = (a0.x + a1.x) * inv + sf.x + bb.x;
    o.y = (a0.y + a1.y) * inv + sf.y + bb.y;
    o.z = (a0.z + a1.z) * inv + sf.z + bb.z;
    o.w = (a0.w + a1.w) * inv + sf.w + bb.w;
    if (do_relu) {
        o.x = fmaxf(o.x, 0.f); o.y = fmaxf(o.y, 0.f);
        o.z = fmaxf(o.z, 0.f); o.w = fmaxf(o.w, 0.f);
    }
    reinterpret_cast<float4*>(out)[(size_t)g * 16 + l] = o;
}

// 16 lanes per supervision edge
__global__ void decode16_k(const float* __restrict__ u_c, const float* __restrict__ u_r,
                           const int* __restrict__ rows, const int* __restrict__ cols,
                           const float* __restrict__ b1, const float* __restrict__ w2,
                           const float* __restrict__ b2, float* __restrict__ out, int L) {
    int g = (blockIdx.x * blockDim.x + threadIdx.x) >> 4;
    int l = threadIdx.x & 15;
    if (g >= L) return;
    int r = __ldg(rows + g);
    int c = __ldg(cols + g);
    float4 a  = reinterpret_cast<const float4*>(u_c)[(size_t)r * 16 + l];
    float4 b  = reinterpret_cast<const float4*>(u_r)[(size_t)c * 16 + l];
    float4 bb = reinterpret_cast<const float4*>(b1)[l];
    float4 w  = reinterpret_cast<const float4*>(w2)[l];
    float h0 = fmaxf(a.x + b.x + bb.x, 0.f);
    float h1 = fmaxf(a.y + b.y + bb.y, 0.f);
    float h2 = fmaxf(a.z + b.z + bb.z, 0.f);
    float h3 = fmaxf(a.w + b.w + bb.w, 0.f);
    float s = (h0 * w.x + h1 * w.y) + (h2 * w.z + h3 * w.w);
#pragma unroll
    for (int off = 8; off; off >>= 1) s += __shfl_xor_sync(0xffffffffu, s, off);
    if (l == 0) out[g] = s + __ldg(b2);
}

// ---------------- launch ----------------

extern "C" void kernel_launch(void* const* d_in, const int* in_sizes, int n_in,
                              void* d_out, int out_size) {
    const float* x_c   = (const float*)d_in[0];
    const float* x_r   = (const float*)d_in[1];
    const float* W1crl = (const float*)d_in[2];
    const float* W1crr = (const float*)d_in[3];
    const float* b1cr  = (const float*)d_in[4];
    const float* W1rcl = (const float*)d_in[5];
    const float* W1rcr = (const float*)d_in[6];
    const float* b1rc  = (const float*)d_in[7];
    const float* W2crl = (const float*)d_in[8];
    const float* W2crr = (const float*)d_in[9];
    const float* b2cr  = (const float*)d_in[10];
    const float* W2rcl = (const float*)d_in[11];
    const float* W2rcr = (const float*)d_in[12];
    const float* b2rc  = (const float*)d_in[13];
    const float* Wd1   = (const float*)d_in[14];
    const float* bd1   = (const float*)d_in[15];
    const float* Wd2   = (const float*)d_in[16];
    const float* bd2   = (const float*)d_in[17];
    const int*   e_cr  = (const int*)d_in[18];
    const int*   e_rc  = (const int*)d_in[19];
    const int*   e_lab = (const int*)d_in[20];
    const int E_ = in_sizes[18] / 2;
    const int L_ = in_sizes[20] / 2;

    uint4 *t_c4, *t_r4;
    float *s_r, *s_c, *h_r, *h_c;
    float *wc_crl, *wc_crr, *wc_rcl, *wc_rcr, *bc_r, *bc_c;
    int *dg_r, *dg_c, *off_r, *off_c, *cur_r, *cur_c, *csr_cr, *csr_rc, *bsum;
    cudaGetSymbolAddress((void**)&t_c4, g_t_c4);
    cudaGetSymbolAddress((void**)&t_r4, g_t_r4);
    cudaGetSymbolAddress((void**)&s_r, g_s_r);
    cudaGetSymbolAddress((void**)&s_c, g_s_c);
    cudaGetSymbolAddress((void**)&h_r, g_h_r);
    cudaGetSymbolAddress((void**)&h_c, g_h_c);
    cudaGetSymbolAddress((void**)&dg_r, g_dg_r);
    cudaGetSymbolAddress((void**)&dg_c, g_dg_c);
    cudaGetSymbolAddress((void**)&off_r, g_off_r);
    cudaGetSymbolAddress((void**)&off_c, g_off_c);
    cudaGetSymbolAddress((void**)&cur_r, g_cur_r);
    cudaGetSymbolAddress((void**)&cur_c, g_cur_c);
    cudaGetSymbolAddress((void**)&csr_cr, g_csr_cr);
    cudaGetSymbolAddress((void**)&csr_rc, g_csr_rc);
    cudaGetSymbolAddress((void**)&bsum, g_bsum);
    cudaGetSymbolAddress((void**)&wc_crl, g_wc_crl);
    cudaGetSymbolAddress((void**)&wc_crr, g_wc_crr);
    cudaGetSymbolAddress((void**)&wc_rcl, g_wc_rcl);
    cudaGetSymbolAddress((void**)&wc_rcr, g_wc_rcr);
    cudaGetSymbolAddress((void**)&bc_r, g_bc_r);
    cudaGetSymbolAddress((void**)&bc_c, g_bc_c);

    const uint2* t_c2 = (const uint2*)t_c4;
    const uint2* t_r2 = (const uint2*)t_r4;

    const int NT = 256;
    const int gRow  = (NCN + NT - 1) / NT;
    const int gE2   = (2 * E_ + NT - 1) / NT;
    const int gZ2   = (2 * (NCN / 4) + NT - 1) / NT;
    const int gN16  = (NCN * 16 + NT - 1) / NT;
    const int gL16  = (L_ * 16 + NT - 1) / NT;

    const int* cr_s = e_cr;   const int* cr_d = e_cr + E_;
    const int* rc_s = e_rc;   const int* rc_d = e_rc + E_;
    const int* lb_r = e_lab;  const int* lb_c = e_lab + L_;

    const float* Wd_top = Wd1;
    const float* Wd_bot = Wd1 + HD * HD;

    // ---- decoder fold ----
    fold_k<<<258, HD>>>(W2crl, W2crr, W2rcl, W2rcr, b2cr, b2rc, Wd_top, Wd_bot,
                        wc_crl, wc_crr, wc_rcl, wc_rcr, bc_r, bc_c);

    // ---- degrees ----
    zero2_k<<<gZ2, NT>>>((int4*)dg_r, (int4*)dg_c, NRN / 4);
    degree2_k<<<gE2, NT>>>(cr_d, dg_r, rc_d, dg_c, E_);

    // ---- CSR build ----
    scan_block2_k<<<2 * NSCANB, SCAN_BS>>>(dg_r, off_r, dg_c, off_c, bsum, NCN);
    scan_sums2_k<<<2, 1024>>>(bsum);
    scan_add_copy2_k<<<2 * NSCANB, SCAN_BS>>>(off_r, cur_r, off_c, cur_c, bsum, NCN);
    csr_fill2_k<<<gE2, NT>>>(cr_s, cr_d, cur_r, csr_cr, rc_s, rc_d, cur_c, csr_rc, E_);

    // ---- layer 1 transforms: messages (fp16 out) + self (fp32 out) ----
    gemm_nk_h<<<gRow, NT, 128 * HD * sizeof(float)>>>(x_c, W1crl, t_c4, NCN, 128);
    gemm_nk  <<<gRow, NT,  64 * HD * sizeof(float)>>>(x_r, W1crr, s_r, NRN, 64);
    gemm_nk_h<<<gRow, NT,  64 * HD * sizeof(float)>>>(x_r, W1rcl, t_r4, NRN, 64);
    gemm_nk  <<<gRow, NT, 128 * HD * sizeof(float)>>>(x_c, W1rcr, s_c, NCN, 128);

    // ---- layer 1 aggregate (relu) ----
    aggregate16_k<<<gN16, NT>>>(t_c2, s_r, b1cr, off_r, dg_r, csr_cr, h_r, NRN, 1);
    aggregate16_k<<<gN16, NT>>>(t_r2, s_c, b1rc, off_c, dg_c, csr_rc, h_c, NCN, 1);

    // ---- layer 2 transforms (decoder-space): messages fp16, self fp32 ----
    gemm_nk_h<<<gRow, NT, 64 * HD * sizeof(float)>>>(h_c, wc_crl, t_c4, NCN, 64);
    gemm_nk  <<<gRow, NT, 64 * HD * sizeof(float)>>>(h_r, wc_crr, s_r, NRN, 64);
    gemm_nk_h<<<gRow, NT, 64 * HD * sizeof(float)>>>(h_r, wc_rcl, t_r4, NRN, 64);
    gemm_nk  <<<gRow, NT, 64 * HD * sizeof(float)>>>(h_c, wc_rcr, s_c, NCN, 64);

    // ---- layer 2 aggregate -> u_r (h_r), u_c (h_c) ----
    aggregate16_k<<<gN16, NT>>>(t_c2, s_r, bc_r, off_r, dg_r, csr_cr, h_r, NRN, 0);
    aggregate16_k<<<gN16, NT>>>(t_r2, s_c, bc_c, off_c, dg_c, csr_rc, h_c, NCN, 0);

    // ---- decode ----
    decode16_k<<<gL16, NT>>>(h_c, h_r, lb_r, lb_c, bd1, Wd2, bd2, (float*)d_out, L_);
}

// round 13
// speedup vs baseline: 1.6413x; 1.0267x over previous
#include <cuda_runtime.h>
#include <cuda_fp16.h>
#include <stdint.h>

#define NCN 100000
#define NRN 100000
#define HD  64
#define EMAX 2000000
#define SCAN_BS 256
#define NSCANB 391   // ceil(100000/256)

// ---------------- scratch (device globals: allocation-free) ----------------
// fp16 message buffers stored as uint4 rows (8 uint4 = 64 halves per row) -> 16B aligned
__device__ uint4  g_t_c4[(size_t)NCN * HD / 8];
__device__ uint4  g_t_r4[(size_t)NRN * HD / 8];
__device__ float  g_s_r[(size_t)NRN * HD];   // self terms (linear access, fp32)
__device__ float  g_s_c[(size_t)NCN * HD];
__device__ float  g_h_r[(size_t)NRN * HD];
__device__ float  g_h_c[(size_t)NCN * HD];
__device__ int    g_dg_r[NRN];
__device__ int    g_dg_c[NCN];
__device__ int    g_off_r[NRN];
__device__ int    g_off_c[NCN];
__device__ int    g_cur_r[NRN];
__device__ int    g_cur_c[NCN];
__device__ int    g_csr_cr[EMAX];
__device__ int    g_csr_rc[EMAX];
__device__ int    g_bsum[2 * NSCANB + 2];
// folded decoder weights/biases
__device__ float  g_wc_crl[HD * HD];
__device__ float  g_wc_crr[HD * HD];
__device__ float  g_wc_rcl[HD * HD];
__device__ float  g_wc_rcr[HD * HD];
__device__ float  g_bc_r[HD];
__device__ float  g_bc_c[HD];

// ---- well-defined fp16 bit packing helpers (no punning) ----
__device__ __forceinline__ unsigned pack_h2(float a, float b) {
    unsigned lo = (unsigned)__half_as_ushort(__float2half_rn(a));
    unsigned hi = (unsigned)__half_as_ushort(__float2half_rn(b));
    return lo | (hi << 16);
}
__device__ __forceinline__ float2 unpack_h2(unsigned w) {
    __half2 h = __halves2half2(__ushort_as_half((unsigned short)(w & 0xFFFFu)),
                               __ushort_as_half((unsigned short)(w >> 16)));
    return __half22float2(h);
}

// ---------------- kernels ----------------

__global__ void zero2_k(int4* __restrict__ a, int4* __restrict__ b, int n4) {
    int i = blockIdx.x * blockDim.x + threadIdx.x;
    if (i < n4) a[i] = make_int4(0, 0, 0, 0);
    else if (i < 2 * n4) b[i - n4] = make_int4(0, 0, 0, 0);
}

__global__ void degree2_k(const int* __restrict__ dstA, int* __restrict__ degA,
                          const int* __restrict__ dstB, int* __restrict__ degB, int nE) {
    int i = blockIdx.x * blockDim.x + threadIdx.x;
    if (i < nE) atomicAdd(degA + __ldg(dstA + i), 1);
    else if (i < 2 * nE) atomicAdd(degB + __ldg(dstB + (i - nE)), 1);
}

// --- segmented 3-kernel exclusive scan: segment 0 = relation A, 1 = relation B ---
__global__ void scan_block2_k(const int* __restrict__ inA, int* __restrict__ outA,
                              const int* __restrict__ inB, int* __restrict__ outB,
                              int* __restrict__ bsum, int n) {
    __shared__ int sh[SCAN_BS];
    int b = blockIdx.x;
    const int* in;
    int* out;
    int lb;
    if (b < NSCANB) { in = inA; out = outA; lb = b; }
    else            { in = inB; out = outB; lb = b - NSCANB; }
    int i = lb * SCAN_BS + threadIdx.x;
    int v = (i < n) ? in[i] : 0;
    sh[threadIdx.x] = v;
    __syncthreads();
    for (int off = 1; off < SCAN_BS; off <<= 1) {
        int t = (threadIdx.x >= off) ? sh[threadIdx.x - off] : 0;
        __syncthreads();
        sh[threadIdx.x] += t;
        __syncthreads();
    }
    if (i < n) out[i] = sh[threadIdx.x] - v;
    if (threadIdx.x == SCAN_BS - 1) bsum[b] = sh[threadIdx.x];
}

__global__ void scan_sums2_k(int* __restrict__ bsum) {
    __shared__ int sh[1024];
    int* seg = bsum + blockIdx.x * NSCANB;
    int v = (threadIdx.x < NSCANB) ? seg[threadIdx.x] : 0;
    sh[threadIdx.x] = v;
    __syncthreads();
    for (int off = 1; off < 1024; off <<= 1) {
        int t = (threadIdx.x >= off) ? sh[threadIdx.x - off] : 0;
        __syncthreads();
        sh[threadIdx.x] += t;
        __syncthreads();
    }
    if (threadIdx.x < NSCANB) seg[threadIdx.x] = sh[threadIdx.x] - v;
}

__global__ void scan_add_copy2_k(int* __restrict__ outA, int* __restrict__ curA,
                                 int* __restrict__ outB, int* __restrict__ curB,
                                 const int* __restrict__ bsum, int n) {
    int b = blockIdx.x;
    int* out;
    int* cur;
    int lb;
    if (b < NSCANB) { out = outA; cur = curA; lb = b; }
    else            { out = outB; cur = curB; lb = b - NSCANB; }
    int i = lb * SCAN_BS + threadIdx.x;
    if (i < n) {
        int v = out[i] + bsum[b];
        out[i] = v;
        cur[i] = v;
    }
}

// both relations' CSR fill (plain src ids)
__global__ void csr_fill2_k(const int* __restrict__ srcA, const int* __restrict__ dstA,
                            int* __restrict__ curA, int* __restrict__ csrA,
                            const int* __restrict__ srcB, const int* __restrict__ dstB,
                            int* __restrict__ curB, int* __restrict__ csrB, int nE) {
    int i = blockIdx.x * blockDim.x + threadIdx.x;
    if (i < nE) {
        int d = __ldg(dstA + i);
        int p = atomicAdd(curA + d, 1);
        csrA[p] = __ldg(srcA + i);
    } else if (i < 2 * nE) {
        int j = i - nE;
        int d = __ldg(dstB + j);
        int p = atomicAdd(curB + d, 1);
        csrB[p] = __ldg(srcB + j);
    }
}

// One launch for the whole decoder fold (258 blocks of 64 threads).
__global__ void fold_k(const float* __restrict__ W2crl, const float* __restrict__ W2crr,
                       const float* __restrict__ W2rcl, const float* __restrict__ W2rcr,
                       const float* __restrict__ b2cr,  const float* __restrict__ b2rc,
                       const float* __restrict__ Wd_top, const float* __restrict__ Wd_bot,
                       float* __restrict__ wc_crl, float* __restrict__ wc_crr,
                       float* __restrict__ wc_rcl, float* __restrict__ wc_rcr,
                       float* __restrict__ bc_r, float* __restrict__ bc_c) {
    __shared__ float Ar[HD];
    int b = blockIdx.x, j = threadIdx.x;
    const float *Arow, *B;
    float* Crow;
    if (b < 256) {
        int which = b >> 6, r = b & 63;
        switch (which) {
            case 0: Arow = W2crl + r * HD; B = Wd_bot; Crow = wc_crl + r * HD; break;
            case 1: Arow = W2crr + r * HD; B = Wd_bot; Crow = wc_crr + r * HD; break;
            case 2: Arow = W2rcl + r * HD; B = Wd_top; Crow = wc_rcl + r * HD; break;
            default:Arow = W2rcr + r * HD; B = Wd_top; Crow = wc_rcr + r * HD; break;
        }
    } else if (b == 256) { Arow = b2cr; B = Wd_bot; Crow = bc_r; }
    else                 { Arow = b2rc; B = Wd_top; Crow = bc_c; }
    Ar[j] = Arow[j];
    __syncthreads();
    float s = 0.f;
#pragma unroll 16
    for (int k = 0; k < HD; k++) s += Ar[k] * B[k * HD + j];
    Crow[j] = s;
}

// Y[n,64] = X[n,K] @ W[K,64], fp32 output.  W cached in shared; one thread per row.
__global__ void gemm_nk(const float* __restrict__ X, const float* __restrict__ W,
                        float* __restrict__ Y, int n, int K) {
    extern __shared__ float Ws[]; // K*64
    for (int i = threadIdx.x; i < K * HD; i += blockDim.x) Ws[i] = W[i];
    __syncthreads();
    int row = blockIdx.x * blockDim.x + threadIdx.x;
    if (row >= n) return;
    float acc[HD];
#pragma unroll
    for (int j = 0; j < HD; j++) acc[j] = 0.f;
    const float* xr = X + (size_t)row * K;
    for (int k = 0; k < K; k += 4) {
        float4 xv = *reinterpret_cast<const float4*>(xr + k);
        float xs[4] = {xv.x, xv.y, xv.z, xv.w};
#pragma unroll
        for (int kk = 0; kk < 4; kk++) {
            const float4* wrow = reinterpret_cast<const float4*>(Ws + (k + kk) * HD);
            float x = xs[kk];
#pragma unroll
            for (int j4 = 0; j4 < HD / 4; j4++) {
                float4 w = wrow[j4];
                acc[j4 * 4 + 0] += x * w.x;
                acc[j4 * 4 + 1] += x * w.y;
                acc[j4 * 4 + 2] += x * w.z;
                acc[j4 * 4 + 3] += x * w.w;
            }
        }
    }
    float4* yr = reinterpret_cast<float4*>(Y + (size_t)row * HD);
#pragma unroll
    for (int j4 = 0; j4 < HD / 4; j4++)
        yr[j4] = make_float4(acc[j4 * 4], acc[j4 * 4 + 1], acc[j4 * 4 + 2], acc[j4 * 4 + 3]);
}

// Same GEMM but fp16-packed output rows (8 uint4 per row), well-defined packing.
__global__ void gemm_nk_h(const float* __restrict__ X, const float* __restrict__ W,
                          uint4* __restrict__ Y4, int n, int K) {
    extern __shared__ float Ws[]; // K*64
    for (int i = threadIdx.x; i < K * HD; i += blockDim.x) Ws[i] = W[i];
    __syncthreads();
    int row = blockIdx.x * blockDim.x + threadIdx.x;
    if (row >= n) return;
    float acc[HD];
#pragma unroll
    for (int j = 0; j < HD; j++) acc[j] = 0.f;
    const float* xr = X + (size_t)row * K;
    for (int k = 0; k < K; k += 4) {
        float4 xv = *reinterpret_cast<const float4*>(xr + k);
        float xs[4] = {xv.x, xv.y, xv.z, xv.w};
#pragma unroll
        for (int kk = 0; kk < 4; kk++) {
            const float4* wrow = reinterpret_cast<const float4*>(Ws + (k + kk) * HD);
            float x = xs[kk];
#pragma unroll
            for (int j4 = 0; j4 < HD / 4; j4++) {
                float4 w = wrow[j4];
                acc[j4 * 4 + 0] += x * w.x;
                acc[j4 * 4 + 1] += x * w.y;
                acc[j4 * 4 + 2] += x * w.z;
                acc[j4 * 4 + 3] += x * w.w;
            }
        }
    }
    uint4* yr = Y4 + (size_t)row * 8;   // 8 uint4 per 64-half row
#pragma unroll
    for (int p = 0; p < 8; p++) {
        uint4 v;
        v.x = pack_h2(acc[8 * p + 0], acc[8 * p + 1]);
        v.y = pack_h2(acc[8 * p + 2], acc[8 * p + 3]);
        v.z = pack_h2(acc[8 * p + 4], acc[8 * p + 5]);
        v.w = pack_h2(acc[8 * p + 6], acc[8 * p + 7]);
        yr[p] = v;
    }
}

// Fused gather-aggregate + mean + self + bias (+relu).
// 16 lanes per dst node; fp16 messages: each lane loads 8B (uint2 = 4 halves) ->
// one 128B line per edge. fp32 accumulation. unroll-2.
__global__ void aggregate16_k(const uint2* __restrict__ feat2, const float* __restrict__ self,
                              const float* __restrict__ bias, const int* __restrict__ offs,
                              const int* __restrict__ deg, const int* __restrict__ csr,
                              float* __restrict__ out, int n, int do_relu) {
    int g = (blockIdx.x * blockDim.x + threadIdx.x) >> 4;
    int l = threadIdx.x & 15;
    if (g >= n) return;
    int beg = __ldg(offs + g);
    int dg  = __ldg(deg + g);
    int end = beg + dg;
    float4 a0 = make_float4(0.f, 0.f, 0.f, 0.f);
    float4 a1 = make_float4(0.f, 0.f, 0.f, 0.f);
    int e = beg;
    for (; e + 1 < end; e += 2) {
        int s0 = __ldg(csr + e);
        int s1 = __ldg(csr + e + 1);
        uint2 v0 = __ldg(feat2 + (size_t)s0 * 16 + l);   // 16 uint2 per row
        uint2 v1 = __ldg(feat2 + (size_t)s1 * 16 + l);
        float2 f00 = unpack_h2(v0.x);
        float2 f01 = unpack_h2(v0.y);
        float2 f10 = unpack_h2(v1.x);
        float2 f11 = unpack_h2(v1.y);
        a0.x += f00.x; a0.y += f00.y; a0.z += f01.x; a0.w += f01.y;
        a1.x += f10.x; a1.y += f10.y; a1.z += f11.x; a1.w += f11.y;
    }
    if (e < end) {
        int s0 = __ldg(csr + e);
        uint2 v0 = __ldg(feat2 + (size_t)s0 * 16 + l);
        float2 f00 = unpack_h2(v0.x);
        float2 f01 = unpack_h2(v0.y);
        a0.x += f00.x; a0.y += f00.y; a0.z += f01.x; a0.w += f01.y;
    }
    float inv = 1.f / (float)max(dg, 1);
    float4 sf = reinterpret_cast<const float4*>(self)[(size_t)g * 16 + l];
    float4 bb = reinterpret_cast<const float4*>(bias)[l];
    float4 o;
    o.x = (a0.x + a1.x) * inv + sf.x + bb.x;
    o.y = (a0.y + a1.y) * inv + sf.y + bb.y;
    o.z = (a0.z + a1.z) * inv + sf.z + bb.z;
    o.w = (a0.w + a1.w) * inv + sf.w + bb.w;
    if (do_relu) {
        o.x = fmaxf(o.x, 0.f); o.y = fmaxf(o.y, 0.f);
        o.z = fmaxf(o.z, 0.f); o.w = fmaxf(o.w, 0.f);
    }
    reinterpret_cast<float4*>(out)[(size_t)g * 16 + l] = o;
}

// 16 lanes per supervision edge
__global__ void decode16_k(const float* __restrict__ u_c, const float* __restrict__ u_r,
                           const int* __restrict__ rows, const int* __restrict__ cols,
                           const float* __restrict__ b1, const float* __restrict__ w2,
                           const float* __restrict__ b2, float* __restrict__ out, int L) {
    int g = (blockIdx.x * blockDim.x + threadIdx.x) >> 4;
    int l = threadIdx.x & 15;
    if (g >= L) return;
    int r = __ldg(rows + g);
    int c = __ldg(cols + g);
    float4 a  = reinterpret_cast<const float4*>(u_c)[(size_t)r * 16 + l];
    float4 b  = reinterpret_cast<const float4*>(u_r)[(size_t)c * 16 + l];
    float4 bb = reinterpret_cast<const float4*>(b1)[l];
    float4 w  = reinterpret_cast<const float4*>(w2)[l];
    float h0 = fmaxf(a.x + b.x + bb.x, 0.f);
    float h1 = fmaxf(a.y + b.y + bb.y, 0.f);
    float h2 = fmaxf(a.z + b.z + bb.z, 0.f);
    float h3 = fmaxf(a.w + b.w + bb.w, 0.f);
    float s = (h0 * w.x + h1 * w.y) + (h2 * w.z + h3 * w.w);
#pragma unroll
    for (int off = 8; off; off >>= 1) s += __shfl_xor_sync(0xffffffffu, s, off);
    if (l == 0) out[g] = s + __ldg(b2);
}

// ---------------- launch ----------------

extern "C" void kernel_launch(void* const* d_in, const int* in_sizes, int n_in,
                              void* d_out, int out_size) {
    const float* x_c   = (const float*)d_in[0];
    const float* x_r   = (const float*)d_in[1];
    const float* W1crl = (const float*)d_in[2];
    const float* W1crr = (const float*)d_in[3];
    const float* b1cr  = (const float*)d_in[4];
    const float* W1rcl = (const float*)d_in[5];
    const float* W1rcr = (const float*)d_in[6];
    const float* b1rc  = (const float*)d_in[7];
    const float* W2crl = (const float*)d_in[8];
    const float* W2crr = (const float*)d_in[9];
    const float* b2cr  = (const float*)d_in[10];
    const float* W2rcl = (const float*)d_in[11];
    const float* W2rcr = (const float*)d_in[12];
    const float* b2rc  = (const float*)d_in[13];
    const float* Wd1   = (const float*)d_in[14];
    const float* bd1   = (const float*)d_in[15];
    const float* Wd2   = (const float*)d_in[16];
    const float* bd2   = (const float*)d_in[17];
    const int*   e_cr  = (const int*)d_in[18];
    const int*   e_rc  = (const int*)d_in[19];
    const int*   e_lab = (const int*)d_in[20];
    const int E_ = in_sizes[18] / 2;
    const int L_ = in_sizes[20] / 2;

    uint4 *t_c4, *t_r4;
    float *s_r, *s_c, *h_r, *h_c;
    float *wc_crl, *wc_crr, *wc_rcl, *wc_rcr, *bc_r, *bc_c;
    int *dg_r, *dg_c, *off_r, *off_c, *cur_r, *cur_c, *csr_cr, *csr_rc, *bsum;
    cudaGetSymbolAddress((void**)&t_c4, g_t_c4);
    cudaGetSymbolAddress((void**)&t_r4, g_t_r4);
    cudaGetSymbolAddress((void**)&s_r, g_s_r);
    cudaGetSymbolAddress((void**)&s_c, g_s_c);
    cudaGetSymbolAddress((void**)&h_r, g_h_r);
    cudaGetSymbolAddress((void**)&h_c, g_h_c);
    cudaGetSymbolAddress((void**)&dg_r, g_dg_r);
    cudaGetSymbolAddress((void**)&dg_c, g_dg_c);
    cudaGetSymbolAddress((void**)&off_r, g_off_r);
    cudaGetSymbolAddress((void**)&off_c, g_off_c);
    cudaGetSymbolAddress((void**)&cur_r, g_cur_r);
    cudaGetSymbolAddress((void**)&cur_c, g_cur_c);
    cudaGetSymbolAddress((void**)&csr_cr, g_csr_cr);
    cudaGetSymbolAddress((void**)&csr_rc, g_csr_rc);
    cudaGetSymbolAddress((void**)&bsum, g_bsum);
    cudaGetSymbolAddress((void**)&wc_crl, g_wc_crl);
    cudaGetSymbolAddress((void**)&wc_crr, g_wc_crr);
    cudaGetSymbolAddress((void**)&wc_rcl, g_wc_rcl);
    cudaGetSymbolAddress((void**)&wc_rcr, g_wc_rcr);
    cudaGetSymbolAddress((void**)&bc_r, g_bc_r);
    cudaGetSymbolAddress((void**)&bc_c, g_bc_c);

    const uint2* t_c2 = (const uint2*)t_c4;
    const uint2* t_r2 = (const uint2*)t_r4;

    // side stream + fork/join events (created once, on the uncaptured correctness call)
    static cudaStream_t s2 = nullptr;
    static cudaEvent_t evFork = nullptr, evJoin = nullptr;
    if (s2 == nullptr) {
        cudaStreamCreateWithFlags(&s2, cudaStreamNonBlocking);
        cudaEventCreateWithFlags(&evFork, cudaEventDisableTiming);
        cudaEventCreateWithFlags(&evJoin, cudaEventDisableTiming);
    }

    const int NT = 256;
    const int gRow  = (NCN + NT - 1) / NT;
    const int gE2   = (2 * E_ + NT - 1) / NT;
    const int gZ2   = (2 * (NCN / 4) + NT - 1) / NT;
    const int gN16  = (NCN * 16 + NT - 1) / NT;
    const int gL16  = (L_ * 16 + NT - 1) / NT;

    const int* cr_s = e_cr;   const int* cr_d = e_cr + E_;
    const int* rc_s = e_rc;   const int* rc_d = e_rc + E_;
    const int* lb_r = e_lab;  const int* lb_c = e_lab + L_;

    const float* Wd_top = Wd1;
    const float* Wd_bot = Wd1 + HD * HD;

    // ======== FORK: CSR build on side stream, GEMMs on main ========
    cudaEventRecord(evFork, 0);
    cudaStreamWaitEvent(s2, evFork, 0);

    // ---- side stream: degrees + CSR build ----
    zero2_k<<<gZ2, NT, 0, s2>>>((int4*)dg_r, (int4*)dg_c, NRN / 4);
    degree2_k<<<gE2, NT, 0, s2>>>(cr_d, dg_r, rc_d, dg_c, E_);
    scan_block2_k<<<2 * NSCANB, SCAN_BS, 0, s2>>>(dg_r, off_r, dg_c, off_c, bsum, NCN);
    scan_sums2_k<<<2, 1024, 0, s2>>>(bsum);
    scan_add_copy2_k<<<2 * NSCANB, SCAN_BS, 0, s2>>>(off_r, cur_r, off_c, cur_c, bsum, NCN);
    csr_fill2_k<<<gE2, NT, 0, s2>>>(cr_s, cr_d, cur_r, csr_cr, rc_s, rc_d, cur_c, csr_rc, E_);
    cudaEventRecord(evJoin, s2);

    // ---- main stream: decoder fold + layer 1 transforms ----
    fold_k<<<258, HD>>>(W2crl, W2crr, W2rcl, W2rcr, b2cr, b2rc, Wd_top, Wd_bot,
                        wc_crl, wc_crr, wc_rcl, wc_rcr, bc_r, bc_c);
    gemm_nk_h<<<gRow, NT, 128 * HD * sizeof(float)>>>(x_c, W1crl, t_c4, NCN, 128);
    gemm_nk  <<<gRow, NT,  64 * HD * sizeof(float)>>>(x_r, W1crr, s_r, NRN, 64);
    gemm_nk_h<<<gRow, NT,  64 * HD * sizeof(float)>>>(x_r, W1rcl, t_r4, NRN, 64);
    gemm_nk  <<<gRow, NT, 128 * HD * sizeof(float)>>>(x_c, W1rcr, s_c, NCN, 128);

    // ======== JOIN before first aggregate ========
    cudaStreamWaitEvent(0, evJoin, 0);

    // ---- layer 1 aggregate (relu) ----
    aggregate16_k<<<gN16, NT>>>(t_c2, s_r, b1cr, off_r, dg_r, csr_cr, h_r, NRN, 1);
    aggregate16_k<<<gN16, NT>>>(t_r2, s_c, b1rc, off_c, dg_c, csr_rc, h_c, NCN, 1);

    // ---- layer 2 transforms (decoder-space): messages fp16, self fp32 ----
    gemm_nk_h<<<gRow, NT, 64 * HD * sizeof(float)>>>(h_c, wc_crl, t_c4, NCN, 64);
    gemm_nk  <<<gRow, NT, 64 * HD * sizeof(float)>>>(h_r, wc_crr, s_r, NRN, 64);
    gemm_nk_h<<<gRow, NT, 64 * HD * sizeof(float)>>>(h_r, wc_rcl, t_r4, NRN, 64);
    gemm_nk  <<<gRow, NT, 64 * HD * sizeof(float)>>>(h_c, wc_rcr, s_c, NCN, 64);

    // ---- layer 2 aggregate -> u_r (h_r), u_c (h_c) ----
    aggregate16_k<<<gN16, NT>>>(t_c2, s_r, bc_r, off_r, dg_r, csr_cr, h_r, NRN, 0);
    aggregate16_k<<<gN16, NT>>>(t_r2, s_c, bc_c, off_c, dg_c, csr_rc, h_c, NCN, 0);

    // ---- decode ----
    decode16_k<<<gL16, NT>>>(h_c, h_r, lb_r, lb_c, bd1, Wd2, bd2, (float*)d_out, L_);
}

// round 15
// speedup vs baseline: 1.9460x; 1.1856x over previous
#include <cuda_runtime.h>
#include <cuda_fp16.h>
#include <stdint.h>

#define NCN 100000
#define NRN 100000
#define HD  64
#define EMAX 2000000
#define SCAN_BS 256
#define NSCANB 391   // ceil(100000/256)

// ---------------- scratch (device globals: allocation-free) ----------------
// fp16 message buffers stored as uint4 rows (8 uint4 = 64 halves per row) -> 16B aligned
__device__ uint4  g_t_c4 [(size_t)NCN * HD / 8];   // layer-1 msg c->r
__device__ uint4  g_t_r4 [(size_t)NRN * HD / 8];   // layer-1 msg r->c
__device__ uint4  g_t_c4b[(size_t)NCN * HD / 8];   // layer-2 msg c->r
__device__ uint4  g_t_r4b[(size_t)NRN * HD / 8];   // layer-2 msg r->c
__device__ float  g_s_r[(size_t)NRN * HD];   // self terms (fp32)
__device__ float  g_s_c[(size_t)NCN * HD];
__device__ float  g_h_r[(size_t)NRN * HD];   // layer-1 outputs
__device__ float  g_h_c[(size_t)NCN * HD];
__device__ float  g_u_r[(size_t)NRN * HD];   // decoder inputs (layer-2 outputs)
__device__ float  g_u_c[(size_t)NCN * HD];
__device__ int    g_dg_r[NRN];
__device__ int    g_dg_c[NCN];
__device__ int    g_off_r[NRN];
__device__ int    g_off_c[NCN];
__device__ int    g_cur_r[NRN];
__device__ int    g_cur_c[NCN];
__device__ int    g_csr_cr[EMAX];
__device__ int    g_csr_rc[EMAX];
__device__ int    g_bsum[2 * NSCANB + 2];
// folded decoder weights/biases
__device__ float  g_wc_crl[HD * HD];
__device__ float  g_wc_crr[HD * HD];
__device__ float  g_wc_rcl[HD * HD];
__device__ float  g_wc_rcr[HD * HD];
__device__ float  g_bc_r[HD];
__device__ float  g_bc_c[HD];

// ---- well-defined fp16 bit packing helpers (no punning) ----
__device__ __forceinline__ unsigned pack_h2(float a, float b) {
    unsigned lo = (unsigned)__half_as_ushort(__float2half_rn(a));
    unsigned hi = (unsigned)__half_as_ushort(__float2half_rn(b));
    return lo | (hi << 16);
}
__device__ __forceinline__ float2 unpack_h2(unsigned w) {
    __half2 h = __halves2half2(__ushort_as_half((unsigned short)(w & 0xFFFFu)),
                               __ushort_as_half((unsigned short)(w >> 16)));
    return __half22float2(h);
}

// ---------------- kernels ----------------

__global__ void zero2_k(int4* __restrict__ a, int4* __restrict__ b, int n4) {
    int i = blockIdx.x * blockDim.x + threadIdx.x;
    if (i < n4) a[i] = make_int4(0, 0, 0, 0);
    else if (i < 2 * n4) b[i - n4] = make_int4(0, 0, 0, 0);
}

__global__ void degree2_k(const int* __restrict__ dstA, int* __restrict__ degA,
                          const int* __restrict__ dstB, int* __restrict__ degB, int nE) {
    int i = blockIdx.x * blockDim.x + threadIdx.x;
    if (i < nE) atomicAdd(degA + __ldg(dstA + i), 1);
    else if (i < 2 * nE) atomicAdd(degB + __ldg(dstB + (i - nE)), 1);
}

// --- segmented 3-kernel exclusive scan ---
__global__ void scan_block2_k(const int* __restrict__ inA, int* __restrict__ outA,
                              const int* __restrict__ inB, int* __restrict__ outB,
                              int* __restrict__ bsum, int n) {
    __shared__ int sh[SCAN_BS];
    int b = blockIdx.x;
    const int* in;
    int* out;
    int lb;
    if (b < NSCANB) { in = inA; out = outA; lb = b; }
    else            { in = inB; out = outB; lb = b - NSCANB; }
    int i = lb * SCAN_BS + threadIdx.x;
    int v = (i < n) ? in[i] : 0;
    sh[threadIdx.x] = v;
    __syncthreads();
    for (int off = 1; off < SCAN_BS; off <<= 1) {
        int t = (threadIdx.x >= off) ? sh[threadIdx.x - off] : 0;
        __syncthreads();
        sh[threadIdx.x] += t;
        __syncthreads();
    }
    if (i < n) out[i] = sh[threadIdx.x] - v;
    if (threadIdx.x == SCAN_BS - 1) bsum[b] = sh[threadIdx.x];
}

__global__ void scan_sums2_k(int* __restrict__ bsum) {
    __shared__ int sh[1024];
    int* seg = bsum + blockIdx.x * NSCANB;
    int v = (threadIdx.x < NSCANB) ? seg[threadIdx.x] : 0;
    sh[threadIdx.x] = v;
    __syncthreads();
    for (int off = 1; off < 1024; off <<= 1) {
        int t = (threadIdx.x >= off) ? sh[threadIdx.x - off] : 0;
        __syncthreads();
        sh[threadIdx.x] += t;
        __syncthreads();
    }
    if (threadIdx.x < NSCANB) seg[threadIdx.x] = sh[threadIdx.x] - v;
}

__global__ void scan_add_copy2_k(int* __restrict__ outA, int* __restrict__ curA,
                                 int* __restrict__ outB, int* __restrict__ curB,
                                 const int* __restrict__ bsum, int n) {
    int b = blockIdx.x;
    int* out;
    int* cur;
    int lb;
    if (b < NSCANB) { out = outA; cur = curA; lb = b; }
    else            { out = outB; cur = curB; lb = b - NSCANB; }
    int i = lb * SCAN_BS + threadIdx.x;
    if (i < n) {
        int v = out[i] + bsum[b];
        out[i] = v;
        cur[i] = v;
    }
}

__global__ void csr_fill2_k(const int* __restrict__ srcA, const int* __restrict__ dstA,
                            int* __restrict__ curA, int* __restrict__ csrA,
                            const int* __restrict__ srcB, const int* __restrict__ dstB,
                            int* __restrict__ curB, int* __restrict__ csrB, int nE) {
    int i = blockIdx.x * blockDim.x + threadIdx.x;
    if (i < nE) {
        int d = __ldg(dstA + i);
        int p = atomicAdd(curA + d, 1);
        csrA[p] = __ldg(srcA + i);
    } else if (i < 2 * nE) {
        int j = i - nE;
        int d = __ldg(dstB + j);
        int p = atomicAdd(curB + d, 1);
        csrB[p] = __ldg(srcB + j);
    }
}

// One launch for the whole decoder fold (258 blocks of 64 threads).
__global__ void fold_k(const float* __restrict__ W2crl, const float* __restrict__ W2crr,
                       const float* __restrict__ W2rcl, const float* __restrict__ W2rcr,
                       const float* __restrict__ b2cr,  const float* __restrict__ b2rc,
                       const float* __restrict__ Wd_top, const float* __restrict__ Wd_bot,
                       float* __restrict__ wc_crl, float* __restrict__ wc_crr,
                       float* __restrict__ wc_rcl, float* __restrict__ wc_rcr,
                       float* __restrict__ bc_r, float* __restrict__ bc_c) {
    __shared__ float Ar[HD];
    int b = blockIdx.x, j = threadIdx.x;
    const float *Arow, *B;
    float* Crow;
    if (b < 256) {
        int which = b >> 6, r = b & 63;
        switch (which) {
            case 0: Arow = W2crl + r * HD; B = Wd_bot; Crow = wc_crl + r * HD; break;
            case 1: Arow = W2crr + r * HD; B = Wd_bot; Crow = wc_crr + r * HD; break;
            case 2: Arow = W2rcl + r * HD; B = Wd_top; Crow = wc_rcl + r * HD; break;
            default:Arow = W2rcr + r * HD; B = Wd_top; Crow = wc_rcr + r * HD; break;
        }
    } else if (b == 256) { Arow = b2cr; B = Wd_bot; Crow = bc_r; }
    else                 { Arow = b2rc; B = Wd_top; Crow = bc_c; }
    Ar[j] = Arow[j];
    __syncthreads();
    float s = 0.f;
#pragma unroll 16
    for (int k = 0; k < HD; k++) s += Ar[k] * B[k * HD + j];
    Crow[j] = s;
}

// Y[n,64] = X[n,K] @ W[K,64], fp32 output.
__global__ void gemm_nk(const float* __restrict__ X, const float* __restrict__ W,
                        float* __restrict__ Y, int n, int K) {
    extern __shared__ float Ws[]; // K*64
    for (int i = threadIdx.x; i < K * HD; i += blockDim.x) Ws[i] = W[i];
    __syncthreads();
    int row = blockIdx.x * blockDim.x + threadIdx.x;
    if (row >= n) return;
    float acc[HD];
#pragma unroll
    for (int j = 0; j < HD; j++) acc[j] = 0.f;
    const float* xr = X + (size_t)row * K;
    for (int k = 0; k < K; k += 4) {
        float4 xv = *reinterpret_cast<const float4*>(xr + k);
        float xs[4] = {xv.x, xv.y, xv.z, xv.w};
#pragma unroll
        for (int kk = 0; kk < 4; kk++) {
            const float4* wrow = reinterpret_cast<const float4*>(Ws + (k + kk) * HD);
            float x = xs[kk];
#pragma unroll
            for (int j4 = 0; j4 < HD / 4; j4++) {
                float4 w = wrow[j4];
                acc[j4 * 4 + 0] += x * w.x;
                acc[j4 * 4 + 1] += x * w.y;
                acc[j4 * 4 + 2] += x * w.z;
                acc[j4 * 4 + 3] += x * w.w;
            }
        }
    }
    float4* yr = reinterpret_cast<float4*>(Y + (size_t)row * HD);
#pragma unroll
    for (int j4 = 0; j4 < HD / 4; j4++)
        yr[j4] = make_float4(acc[j4 * 4], acc[j4 * 4 + 1], acc[j4 * 4 + 2], acc[j4 * 4 + 3]);
}

// Same GEMM but fp16-packed output rows (8 uint4 per row).
__global__ void gemm_nk_h(const float* __restrict__ X, const float* __restrict__ W,
                          uint4* __restrict__ Y4, int n, int K) {
    extern __shared__ float Ws[]; // K*64
    for (int i = threadIdx.x; i < K * HD; i += blockDim.x) Ws[i] = W[i];
    __syncthreads();
    int row = blockIdx.x * blockDim.x + threadIdx.x;
    if (row >= n) return;
    float acc[HD];
#pragma unroll
    for (int j = 0; j < HD; j++) acc[j] = 0.f;
    const float* xr = X + (size_t)row * K;
    for (int k = 0; k < K; k += 4) {
        float4 xv = *reinterpret_cast<const float4*>(xr + k);
        float xs[4] = {xv.x, xv.y, xv.z, xv.w};
#pragma unroll
        for (int kk = 0; kk < 4; kk++) {
            const float4* wrow = reinterpret_cast<const float4*>(Ws + (k + kk) * HD);
            float x = xs[kk];
#pragma unroll
            for (int j4 = 0; j4 < HD / 4; j4++) {
                float4 w = wrow[j4];
                acc[j4 * 4 + 0] += x * w.x;
                acc[j4 * 4 + 1] += x * w.y;
                acc[j4 * 4 + 2] += x * w.z;
                acc[j4 * 4 + 3] += x * w.w;
            }
        }
    }
    uint4* yr = Y4 + (size_t)row * 8;
#pragma unroll
    for (int p = 0; p < 8; p++) {
        uint4 v;
        v.x = pack_h2(acc[8 * p + 0], acc[8 * p + 1]);
        v.y = pack_h2(acc[8 * p + 2], acc[8 * p + 3]);
        v.z = pack_h2(acc[8 * p + 4], acc[8 * p + 5]);
        v.w = pack_h2(acc[8 * p + 6], acc[8 * p + 7]);
        yr[p] = v;
    }
}

// Fused gather-aggregate + mean + self + bias (+relu). 16 lanes/node, fp16 msgs.
__global__ void aggregate16_k(const uint2* __restrict__ feat2, const float* __restrict__ self,
                              const float* __restrict__ bias, const int* __restrict__ offs,
                              const int* __restrict__ deg, const int* __restrict__ csr,
                              float* __restrict__ out, int n, int do_relu) {
    int g = (blockIdx.x * blockDim.x + threadIdx.x) >> 4;
    int l = threadIdx.x & 15;
    if (g >= n) return;
    int beg = __ldg(offs + g);
    int dg  = __ldg(deg + g);
    int end = beg + dg;
    float4 a0 = make_float4(0.f, 0.f, 0.f, 0.f);
    float4 a1 = make_float4(0.f, 0.f, 0.f, 0.f);
    int e = beg;
    for (; e + 1 < end; e += 2) {
        int s0 = __ldg(csr + e);
        int s1 = __ldg(csr + e + 1);
        uint2 v0 = __ldg(feat2 + (size_t)s0 * 16 + l);
        uint2 v1 = __ldg(feat2 + (size_t)s1 * 16 + l);
        float2 f00 = unpack_h2(v0.x);
        float2 f01 = unpack_h2(v0.y);
        float2 f10 = unpack_h2(v1.x);
        float2 f11 = unpack_h2(v1.y);
        a0.x += f00.x; a0.y += f00.y; a0.z += f01.x; a0.w += f01.y;
        a1.x += f10.x; a1.y += f10.y; a1.z += f11.x; a1.w += f11.y;
    }
    if (e < end) {
        int s0 = __ldg(csr + e);
        uint2 v0 = __ldg(feat2 + (size_t)s0 * 16 + l);
        float2 f00 = unpack_h2(v0.x);
        float2 f01 = unpack_h2(v0.y);
        a0.x += f00.x; a0.y += f00.y; a0.z += f01.x; a0.w += f01.y;
    }
    float inv = 1.f / (float)max(dg, 1);
    float4 sf = reinterpret_cast<const float4*>(self)[(size_t)g * 16 + l];
    float4 bb = reinterpret_cast<const float4*>(bias)[l];
    float4 o;
    o.x = (a0.x + a1.x) * inv + sf.x + bb.x;
    o.y = (a0.y + a1.y) * inv + sf.y + bb.y;
    o.z = (a0.z + a1.z) * inv + sf.z + bb.z;
    o.w = (a0.w + a1.w) * inv + sf.w + bb.w;
    if (do_relu) {
        o.x = fmaxf(o.x, 0.f); o.y = fmaxf(o.y, 0.f);
        o.z = fmaxf(o.z, 0.f); o.w = fmaxf(o.w, 0.f);
    }
    reinterpret_cast<float4*>(out)[(size_t)g * 16 + l] = o;
}

// 16 lanes per supervision edge
__global__ void decode16_k(const float* __restrict__ u_c, const float* __restrict__ u_r,
                           const int* __restrict__ rows, const int* __restrict__ cols,
                           const float* __restrict__ b1, const float* __restrict__ w2,
                           const float* __restrict__ b2, float* __restrict__ out, int L) {
    int g = (blockIdx.x * blockDim.x + threadIdx.x) >> 4;
    int l = threadIdx.x & 15;
    if (g >= L) return;
    int r = __ldg(rows + g);
    int c = __ldg(cols + g);
    float4 a  = reinterpret_cast<const float4*>(u_c)[(size_t)r * 16 + l];
    float4 b  = reinterpret_cast<const float4*>(u_r)[(size_t)c * 16 + l];
    float4 bb = reinterpret_cast<const float4*>(b1)[l];
    float4 w  = reinterpret_cast<const float4*>(w2)[l];
    float h0 = fmaxf(a.x + b.x + bb.x, 0.f);
    float h1 = fmaxf(a.y + b.y + bb.y, 0.f);
    float h2 = fmaxf(a.z + b.z + bb.z, 0.f);
    float h3 = fmaxf(a.w + b.w + bb.w, 0.f);
    float s = (h0 * w.x + h1 * w.y) + (h2 * w.z + h3 * w.w);
#pragma unroll
    for (int off = 8; off; off >>= 1) s += __shfl_xor_sync(0xffffffffu, s, off);
    if (l == 0) out[g] = s + __ldg(b2);
}

// ---------------- launch ----------------

extern "C" void kernel_launch(void* const* d_in, const int* in_sizes, int n_in,
                              void* d_out, int out_size) {
    const float* x_c   = (const float*)d_in[0];
    const float* x_r   = (const float*)d_in[1];
    const float* W1crl = (const float*)d_in[2];
    const float* W1crr = (const float*)d_in[3];
    const float* b1cr  = (const float*)d_in[4];
    const float* W1rcl = (const float*)d_in[5];
    const float* W1rcr = (const float*)d_in[6];
    const float* b1rc  = (const float*)d_in[7];
    const float* W2crl = (const float*)d_in[8];
    const float* W2crr = (const float*)d_in[9];
    const float* b2cr  = (const float*)d_in[10];
    const float* W2rcl = (const float*)d_in[11];
    const float* W2rcr = (const float*)d_in[12];
    const float* b2rc  = (const float*)d_in[13];
    const float* Wd1   = (const float*)d_in[14];
    const float* bd1   = (const float*)d_in[15];
    const float* Wd2   = (const float*)d_in[16];
    const float* bd2   = (const float*)d_in[17];
    const int*   e_cr  = (const int*)d_in[18];
    const int*   e_rc  = (const int*)d_in[19];
    const int*   e_lab = (const int*)d_in[20];
    const int E_ = in_sizes[18] / 2;
    const int L_ = in_sizes[20] / 2;

    uint4 *t_c4, *t_r4, *t_c4b, *t_r4b;
    float *s_r, *s_c, *h_r, *h_c, *u_r, *u_c;
    float *wc_crl, *wc_crr, *wc_rcl, *wc_rcr, *bc_r, *bc_c;
    int *dg_r, *dg_c, *off_r, *off_c, *cur_r, *cur_c, *csr_cr, *csr_rc, *bsum;
    cudaGetSymbolAddress((void**)&t_c4, g_t_c4);
    cudaGetSymbolAddress((void**)&t_r4, g_t_r4);
    cudaGetSymbolAddress((void**)&t_c4b, g_t_c4b);
    cudaGetSymbolAddress((void**)&t_r4b, g_t_r4b);
    cudaGetSymbolAddress((void**)&s_r, g_s_r);
    cudaGetSymbolAddress((void**)&s_c, g_s_c);
    cudaGetSymbolAddress((void**)&h_r, g_h_r);
    cudaGetSymbolAddress((void**)&h_c, g_h_c);
    cudaGetSymbolAddress((void**)&u_r, g_u_r);
    cudaGetSymbolAddress((void**)&u_c, g_u_c);
    cudaGetSymbolAddress((void**)&dg_r, g_dg_r);
    cudaGetSymbolAddress((void**)&dg_c, g_dg_c);
    cudaGetSymbolAddress((void**)&off_r, g_off_r);
    cudaGetSymbolAddress((void**)&off_c, g_off_c);
    cudaGetSymbolAddress((void**)&cur_r, g_cur_r);
    cudaGetSymbolAddress((void**)&cur_c, g_cur_c);
    cudaGetSymbolAddress((void**)&csr_cr, g_csr_cr);
    cudaGetSymbolAddress((void**)&csr_rc, g_csr_rc);
    cudaGetSymbolAddress((void**)&bsum, g_bsum);
    cudaGetSymbolAddress((void**)&wc_crl, g_wc_crl);
    cudaGetSymbolAddress((void**)&wc_crr, g_wc_crr);
    cudaGetSymbolAddress((void**)&wc_rcl, g_wc_rcl);
    cudaGetSymbolAddress((void**)&wc_rcr, g_wc_rcr);
    cudaGetSymbolAddress((void**)&bc_r, g_bc_r);
    cudaGetSymbolAddress((void**)&bc_c, g_bc_c);

    const uint2* t_c2  = (const uint2*)t_c4;
    const uint2* t_r2  = (const uint2*)t_r4;
    const uint2* t_c2b = (const uint2*)t_c4b;
    const uint2* t_r2b = (const uint2*)t_r4b;

    // side stream + events (created once, on the uncaptured correctness call)
    static cudaStream_t s2 = nullptr;
    static cudaEvent_t evFork = nullptr, evCSR = nullptr, evA2 = nullptr,
                       evG7 = nullptr, evA4 = nullptr;
    if (s2 == nullptr) {
        cudaStreamCreateWithFlags(&s2, cudaStreamNonBlocking);
        cudaEventCreateWithFlags(&evFork, cudaEventDisableTiming);
        cudaEventCreateWithFlags(&evCSR, cudaEventDisableTiming);
        cudaEventCreateWithFlags(&evA2, cudaEventDisableTiming);
        cudaEventCreateWithFlags(&evG7, cudaEventDisableTiming);
        cudaEventCreateWithFlags(&evA4, cudaEventDisableTiming);
    }

    const int NT = 256;
    const int gRow  = (NCN + NT - 1) / NT;
    const int gE2   = (2 * E_ + NT - 1) / NT;
    const int gZ2   = (2 * (NCN / 4) + NT - 1) / NT;
    const int gN16  = (NCN * 16 + NT - 1) / NT;
    const int gL16  = (L_ * 16 + NT - 1) / NT;

    const int* cr_s = e_cr;   const int* cr_d = e_cr + E_;
    const int* rc_s = e_rc;   const int* rc_d = e_rc + E_;
    const int* lb_r = e_lab;  const int* lb_c = e_lab + L_;

    const float* Wd_top = Wd1;
    const float* Wd_bot = Wd1 + HD * HD;

    // ======== FORK ========
    cudaEventRecord(evFork, 0);
    cudaStreamWaitEvent(s2, evFork, 0);

    // ---- [1] s2: CSR build -> evCSR; G3, G4, A2 -> evA2 ----
    zero2_k<<<gZ2, NT, 0, s2>>>((int4*)dg_r, (int4*)dg_c, NRN / 4);
    degree2_k<<<gE2, NT, 0, s2>>>(cr_d, dg_r, rc_d, dg_c, E_);
    scan_block2_k<<<2 * NSCANB, SCAN_BS, 0, s2>>>(dg_r, off_r, dg_c, off_c, bsum, NCN);
    scan_sums2_k<<<2, 1024, 0, s2>>>(bsum);
    scan_add_copy2_k<<<2 * NSCANB, SCAN_BS, 0, s2>>>(off_r, cur_r, off_c, cur_c, bsum, NCN);
    csr_fill2_k<<<gE2, NT, 0, s2>>>(cr_s, cr_d, cur_r, csr_cr, rc_s, rc_d, cur_c, csr_rc, E_);
    cudaEventRecord(evCSR, s2);
    gemm_nk_h<<<gRow, NT, 64 * HD * sizeof(float), s2>>>(x_r, W1rcl, t_r4, NRN, 64);
    gemm_nk  <<<gRow, NT, 128 * HD * sizeof(float), s2>>>(x_c, W1rcr, s_c, NCN, 128);
    aggregate16_k<<<gN16, NT, 0, s2>>>(t_r2, s_c, b1rc, off_c, dg_c, csr_rc, h_c, NCN, 1);
    cudaEventRecord(evA2, s2);

    // ---- [2] main: fold, G1, G2; wait evCSR; A1; G6, G7 -> evG7 ----
    fold_k<<<258, HD>>>(W2crl, W2crr, W2rcl, W2rcr, b2cr, b2rc, Wd_top, Wd_bot,
                        wc_crl, wc_crr, wc_rcl, wc_rcr, bc_r, bc_c);
    gemm_nk_h<<<gRow, NT, 128 * HD * sizeof(float)>>>(x_c, W1crl, t_c4, NCN, 128);
    gemm_nk  <<<gRow, NT,  64 * HD * sizeof(float)>>>(x_r, W1crr, s_r, NRN, 64);
    cudaStreamWaitEvent(0, evCSR, 0);
    aggregate16_k<<<gN16, NT>>>(t_c2, s_r, b1cr, off_r, dg_r, csr_cr, h_r, NRN, 1);
    gemm_nk  <<<gRow, NT, 64 * HD * sizeof(float)>>>(h_r, wc_crr, s_r, NRN, 64);
    gemm_nk_h<<<gRow, NT, 64 * HD * sizeof(float)>>>(h_r, wc_rcl, t_r4b, NRN, 64);
    cudaEventRecord(evG7, 0);

    // ---- [3] s2: G8; wait evG7; A4 -> evA4 ----
    gemm_nk<<<gRow, NT, 64 * HD * sizeof(float), s2>>>(h_c, wc_rcr, s_c, NCN, 64);
    cudaStreamWaitEvent(s2, evG7, 0);
    aggregate16_k<<<gN16, NT, 0, s2>>>(t_r2b, s_c, bc_c, off_c, dg_c, csr_rc, u_c, NCN, 0);
    cudaEventRecord(evA4, s2);

    // ---- [4] main: wait evA2; G5; A3; wait evA4; decode ----
    cudaStreamWaitEvent(0, evA2, 0);
    gemm_nk_h<<<gRow, NT, 64 * HD * sizeof(float)>>>(h_c, wc_crl, t_c4b, NCN, 64);
    aggregate16_k<<<gN16, NT>>>(t_c2b, s_r, bc_r, off_r, dg_r, csr_cr, u_r, NRN, 0);
    cudaStreamWaitEvent(0, evA4, 0);
    decode16_k<<<gL16, NT>>>(u_c, u_r, lb_r, lb_c, bd1, Wd2, bd2, (float*)d_out, L_);
}

// round 16
// speedup vs baseline: 1.9568x; 1.0056x over previous
#include <cuda_runtime.h>
#include <cuda_fp16.h>
#include <stdint.h>

#define NCN 100000
#define NRN 100000
#define HD  64
#define EMAX 2000000
#define SCAN_BS 256
#define NSCANB 391   // ceil(100000/256)

// ---------------- scratch (device globals: allocation-free) ----------------
// fp16 message buffers stored as uint4 rows (8 uint4 = 64 halves per row) -> 16B aligned
__device__ uint4  g_t_c4 [(size_t)NCN * HD / 8];   // layer-1 msg c->r
__device__ uint4  g_t_r4 [(size_t)NRN * HD / 8];   // layer-1 msg r->c
__device__ uint4  g_t_c4b[(size_t)NCN * HD / 8];   // layer-2 msg c->r
__device__ uint4  g_t_r4b[(size_t)NRN * HD / 8];   // layer-2 msg r->c
__device__ float  g_s_r[(size_t)NRN * HD];   // self terms (fp32)
__device__ float  g_s_c[(size_t)NCN * HD];
__device__ float  g_h_r[(size_t)NRN * HD];   // layer-1 outputs
__device__ float  g_h_c[(size_t)NCN * HD];
__device__ float  g_u_r[(size_t)NRN * HD];   // decoder inputs (layer-2 outputs)
__device__ float  g_u_c[(size_t)NCN * HD];
__device__ int    g_dg_r[NRN];
__device__ int    g_dg_c[NCN];
__device__ int    g_off_r[NRN];
__device__ int    g_off_c[NCN];
__device__ int    g_cur_r[NRN];
__device__ int    g_cur_c[NCN];
__device__ int    g_csr_cr[EMAX];
__device__ int    g_csr_rc[EMAX];
__device__ int    g_bsum[2 * NSCANB + 2];
// folded decoder weights/biases
__device__ float  g_wc_crl[HD * HD];
__device__ float  g_wc_crr[HD * HD];
__device__ float  g_wc_rcl[HD * HD];
__device__ float  g_wc_rcr[HD * HD];
__device__ float  g_bc_r[HD];
__device__ float  g_bc_c[HD];

// ---- well-defined fp16 bit packing helpers (no punning) ----
__device__ __forceinline__ unsigned pack_h2(float a, float b) {
    unsigned lo = (unsigned)__half_as_ushort(__float2half_rn(a));
    unsigned hi = (unsigned)__half_as_ushort(__float2half_rn(b));
    return lo | (hi << 16);
}
__device__ __forceinline__ float2 unpack_h2(unsigned w) {
    __half2 h = __halves2half2(__ushort_as_half((unsigned short)(w & 0xFFFFu)),
                               __ushort_as_half((unsigned short)(w >> 16)));
    return __half22float2(h);
}

// ---------------- kernels ----------------

__global__ void zero2_k(int4* __restrict__ a, int4* __restrict__ b, int n4) {
    int i = blockIdx.x * blockDim.x + threadIdx.x;
    if (i < n4) a[i] = make_int4(0, 0, 0, 0);
    else if (i < 2 * n4) b[i - n4] = make_int4(0, 0, 0, 0);
}

__global__ void degree2_k(const int* __restrict__ dstA, int* __restrict__ degA,
                          const int* __restrict__ dstB, int* __restrict__ degB, int nE) {
    int i = blockIdx.x * blockDim.x + threadIdx.x;
    if (i < nE) atomicAdd(degA + __ldg(dstA + i), 1);
    else if (i < 2 * nE) atomicAdd(degB + __ldg(dstB + (i - nE)), 1);
}

// --- segmented 3-kernel exclusive scan ---
__global__ void scan_block2_k(const int* __restrict__ inA, int* __restrict__ outA,
                              const int* __restrict__ inB, int* __restrict__ outB,
                              int* __restrict__ bsum, int n) {
    __shared__ int sh[SCAN_BS];
    int b = blockIdx.x;
    const int* in;
    int* out;
    int lb;
    if (b < NSCANB) { in = inA; out = outA; lb = b; }
    else            { in = inB; out = outB; lb = b - NSCANB; }
    int i = lb * SCAN_BS + threadIdx.x;
    int v = (i < n) ? in[i] : 0;
    sh[threadIdx.x] = v;
    __syncthreads();
    for (int off = 1; off < SCAN_BS; off <<= 1) {
        int t = (threadIdx.x >= off) ? sh[threadIdx.x - off] : 0;
        __syncthreads();
        sh[threadIdx.x] += t;
        __syncthreads();
    }
    if (i < n) out[i] = sh[threadIdx.x] - v;
    if (threadIdx.x == SCAN_BS - 1) bsum[b] = sh[threadIdx.x];
}

__global__ void scan_sums2_k(int* __restrict__ bsum) {
    __shared__ int sh[1024];
    int* seg = bsum + blockIdx.x * NSCANB;
    int v = (threadIdx.x < NSCANB) ? seg[threadIdx.x] : 0;
    sh[threadIdx.x] = v;
    __syncthreads();
    for (int off = 1; off < 1024; off <<= 1) {
        int t = (threadIdx.x >= off) ? sh[threadIdx.x - off] : 0;
        __syncthreads();
        sh[threadIdx.x] += t;
        __syncthreads();
    }
    if (threadIdx.x < NSCANB) seg[threadIdx.x] = sh[threadIdx.x] - v;
}

__global__ void scan_add_copy2_k(int* __restrict__ outA, int* __restrict__ curA,
                                 int* __restrict__ outB, int* __restrict__ curB,
                                 const int* __restrict__ bsum, int n) {
    int b = blockIdx.x;
    int* out;
    int* cur;
    int lb;
    if (b < NSCANB) { out = outA; cur = curA; lb = b; }
    else            { out = outB; cur = curB; lb = b - NSCANB; }
    int i = lb * SCAN_BS + threadIdx.x;
    if (i < n) {
        int v = out[i] + bsum[b];
        out[i] = v;
        cur[i] = v;
    }
}

__global__ void csr_fill2_k(const int* __restrict__ srcA, const int* __restrict__ dstA,
                            int* __restrict__ curA, int* __restrict__ csrA,
                            const int* __restrict__ srcB, const int* __restrict__ dstB,
                            int* __restrict__ curB, int* __restrict__ csrB, int nE) {
    int i = blockIdx.x * blockDim.x + threadIdx.x;
    if (i < nE) {
        int d = __ldg(dstA + i);
        int p = atomicAdd(curA + d, 1);
        csrA[p] = __ldg(srcA + i);
    } else if (i < 2 * nE) {
        int j = i - nE;
        int d = __ldg(dstB + j);
        int p = atomicAdd(curB + d, 1);
        csrB[p] = __ldg(srcB + j);
    }
}

// One launch for the whole decoder fold (258 blocks of 64 threads).
__global__ void fold_k(const float* __restrict__ W2crl, const float* __restrict__ W2crr,
                       const float* __restrict__ W2rcl, const float* __restrict__ W2rcr,
                       const float* __restrict__ b2cr,  const float* __restrict__ b2rc,
                       const float* __restrict__ Wd_top, const float* __restrict__ Wd_bot,
                       float* __restrict__ wc_crl, float* __restrict__ wc_crr,
                       float* __restrict__ wc_rcl, float* __restrict__ wc_rcr,
                       float* __restrict__ bc_r, float* __restrict__ bc_c) {
    __shared__ float Ar[HD];
    int b = blockIdx.x, j = threadIdx.x;
    const float *Arow, *B;
    float* Crow;
    if (b < 256) {
        int which = b >> 6, r = b & 63;
        switch (which) {
            case 0: Arow = W2crl + r * HD; B = Wd_bot; Crow = wc_crl + r * HD; break;
            case 1: Arow = W2crr + r * HD; B = Wd_bot; Crow = wc_crr + r * HD; break;
            case 2: Arow = W2rcl + r * HD; B = Wd_top; Crow = wc_rcl + r * HD; break;
            default:Arow = W2rcr + r * HD; B = Wd_top; Crow = wc_rcr + r * HD; break;
        }
    } else if (b == 256) { Arow = b2cr; B = Wd_bot; Crow = bc_r; }
    else                 { Arow = b2rc; B = Wd_top; Crow = bc_c; }
    Ar[j] = Arow[j];
    __syncthreads();
    float s = 0.f;
#pragma unroll 16
    for (int k = 0; k < HD; k++) s += Ar[k] * B[k * HD + j];
    Crow[j] = s;
}

// Y[n,64] = X[n,K] @ W[K,64], fp32 output.
__global__ void gemm_nk(const float* __restrict__ X, const float* __restrict__ W,
                        float* __restrict__ Y, int n, int K) {
    extern __shared__ float Ws[]; // K*64
    for (int i = threadIdx.x; i < K * HD; i += blockDim.x) Ws[i] = W[i];
    __syncthreads();
    int row = blockIdx.x * blockDim.x + threadIdx.x;
    if (row >= n) return;
    float acc[HD];
#pragma unroll
    for (int j = 0; j < HD; j++) acc[j] = 0.f;
    const float* xr = X + (size_t)row * K;
    for (int k = 0; k < K; k += 4) {
        float4 xv = *reinterpret_cast<const float4*>(xr + k);
        float xs[4] = {xv.x, xv.y, xv.z, xv.w};
#pragma unroll
        for (int kk = 0; kk < 4; kk++) {
            const float4* wrow = reinterpret_cast<const float4*>(Ws + (k + kk) * HD);
            float x = xs[kk];
#pragma unroll
            for (int j4 = 0; j4 < HD / 4; j4++) {
                float4 w = wrow[j4];
                acc[j4 * 4 + 0] += x * w.x;
                acc[j4 * 4 + 1] += x * w.y;
                acc[j4 * 4 + 2] += x * w.z;
                acc[j4 * 4 + 3] += x * w.w;
            }
        }
    }
    float4* yr = reinterpret_cast<float4*>(Y + (size_t)row * HD);
#pragma unroll
    for (int j4 = 0; j4 < HD / 4; j4++)
        yr[j4] = make_float4(acc[j4 * 4], acc[j4 * 4 + 1], acc[j4 * 4 + 2], acc[j4 * 4 + 3]);
}

// Same GEMM but fp16-packed output rows (8 uint4 per row).
__global__ void gemm_nk_h(const float* __restrict__ X, const float* __restrict__ W,
                          uint4* __restrict__ Y4, int n, int K) {
    extern __shared__ float Ws[]; // K*64
    for (int i = threadIdx.x; i < K * HD; i += blockDim.x) Ws[i] = W[i];
    __syncthreads();
    int row = blockIdx.x * blockDim.x + threadIdx.x;
    if (row >= n) return;
    float acc[HD];
#pragma unroll
    for (int j = 0; j < HD; j++) acc[j] = 0.f;
    const float* xr = X + (size_t)row * K;
    for (int k = 0; k < K; k += 4) {
        float4 xv = *reinterpret_cast<const float4*>(xr + k);
        float xs[4] = {xv.x, xv.y, xv.z, xv.w};
#pragma unroll
        for (int kk = 0; kk < 4; kk++) {
            const float4* wrow = reinterpret_cast<const float4*>(Ws + (k + kk) * HD);
            float x = xs[kk];
#pragma unroll
            for (int j4 = 0; j4 < HD / 4; j4++) {
                float4 w = wrow[j4];
                acc[j4 * 4 + 0] += x * w.x;
                acc[j4 * 4 + 1] += x * w.y;
                acc[j4 * 4 + 2] += x * w.z;
                acc[j4 * 4 + 3] += x * w.w;
            }
        }
    }
    uint4* yr = Y4 + (size_t)row * 8;
#pragma unroll
    for (int p = 0; p < 8; p++) {
        uint4 v;
        v.x = pack_h2(acc[8 * p + 0], acc[8 * p + 1]);
        v.y = pack_h2(acc[8 * p + 2], acc[8 * p + 3]);
        v.z = pack_h2(acc[8 * p + 4], acc[8 * p + 5]);
        v.w = pack_h2(acc[8 * p + 6], acc[8 * p + 7]);
        yr[p] = v;
    }
}

// Fused gather-aggregate + mean + self + bias (+relu). 16 lanes/node, fp16 msgs.
__global__ void aggregate16_k(const uint2* __restrict__ feat2, const float* __restrict__ self,
                              const float* __restrict__ bias, const int* __restrict__ offs,
                              const int* __restrict__ deg, const int* __restrict__ csr,
                              float* __restrict__ out, int n, int do_relu) {
    int g = (blockIdx.x * blockDim.x + threadIdx.x) >> 4;
    int l = threadIdx.x & 15;
    if (g >= n) return;
    int beg = __ldg(offs + g);
    int dg  = __ldg(deg + g);
    int end = beg + dg;
    float4 a0 = make_float4(0.f, 0.f, 0.f, 0.f);
    float4 a1 = make_float4(0.f, 0.f, 0.f, 0.f);
    int e = beg;
    for (; e + 1 < end; e += 2) {
        int s0 = __ldg(csr + e);
        int s1 = __ldg(csr + e + 1);
        uint2 v0 = __ldg(feat2 + (size_t)s0 * 16 + l);
        uint2 v1 = __ldg(feat2 + (size_t)s1 * 16 + l);
        float2 f00 = unpack_h2(v0.x);
        float2 f01 = unpack_h2(v0.y);
        float2 f10 = unpack_h2(v1.x);
        float2 f11 = unpack_h2(v1.y);
        a0.x += f00.x; a0.y += f00.y; a0.z += f01.x; a0.w += f01.y;
        a1.x += f10.x; a1.y += f10.y; a1.z += f11.x; a1.w += f11.y;
    }
    if (e < end) {
        int s0 = __ldg(csr + e);
        uint2 v0 = __ldg(feat2 + (size_t)s0 * 16 + l);
        float2 f00 = unpack_h2(v0.x);
        float2 f01 = unpack_h2(v0.y);
        a0.x += f00.x; a0.y += f00.y; a0.z += f01.x; a0.w += f01.y;
    }
    float inv = 1.f / (float)max(dg, 1);
    float4 sf = reinterpret_cast<const float4*>(self)[(size_t)g * 16 + l];
    float4 bb = reinterpret_cast<const float4*>(bias)[l];
    float4 o;
    o.x = (a0.x + a1.x) * inv + sf.x + bb.x;
    o.y = (a0.y + a1.y) * inv + sf.y + bb.y;
    o.z = (a0.z + a1.z) * inv + sf.z + bb.z;
    o.w = (a0.w + a1.w) * inv + sf.w + bb.w;
    if (do_relu) {
        o.x = fmaxf(o.x, 0.f); o.y = fmaxf(o.y, 0.f);
        o.z = fmaxf(o.z, 0.f); o.w = fmaxf(o.w, 0.f);
    }
    reinterpret_cast<float4*>(out)[(size_t)g * 16 + l] = o;
}

// 16 lanes per supervision edge
__global__ void decode16_k(const float* __restrict__ u_c, const float* __restrict__ u_r,
                           const int* __restrict__ rows, const int* __restrict__ cols,
                           const float* __restrict__ b1, const float* __restrict__ w2,
                           const float* __restrict__ b2, float* __restrict__ out, int L) {
    int g = (blockIdx.x * blockDim.x + threadIdx.x) >> 4;
    int l = threadIdx.x & 15;
    if (g >= L) return;
    int r = __ldg(rows + g);
    int c = __ldg(cols + g);
    float4 a  = reinterpret_cast<const float4*>(u_c)[(size_t)r * 16 + l];
    float4 b  = reinterpret_cast<const float4*>(u_r)[(size_t)c * 16 + l];
    float4 bb = reinterpret_cast<const float4*>(b1)[l];
    float4 w  = reinterpret_cast<const float4*>(w2)[l];
    float h0 = fmaxf(a.x + b.x + bb.x, 0.f);
    float h1 = fmaxf(a.y + b.y + bb.y, 0.f);
    float h2 = fmaxf(a.z + b.z + bb.z, 0.f);
    float h3 = fmaxf(a.w + b.w + bb.w, 0.f);
    float s = (h0 * w.x + h1 * w.y) + (h2 * w.z + h3 * w.w);
#pragma unroll
    for (int off = 8; off; off >>= 1) s += __shfl_xor_sync(0xffffffffu, s, off);
    if (l == 0) out[g] = s + __ldg(b2);
}

// ---------------- launch ----------------

extern "C" void kernel_launch(void* const* d_in, const int* in_sizes, int n_in,
                              void* d_out, int out_size) {
    const float* x_c   = (const float*)d_in[0];
    const float* x_r   = (const float*)d_in[1];
    const float* W1crl = (const float*)d_in[2];
    const float* W1crr = (const float*)d_in[3];
    const float* b1cr  = (const float*)d_in[4];
    const float* W1rcl = (const float*)d_in[5];
    const float* W1rcr = (const float*)d_in[6];
    const float* b1rc  = (const float*)d_in[7];
    const float* W2crl = (const float*)d_in[8];
    const float* W2crr = (const float*)d_in[9];
    const float* b2cr  = (const float*)d_in[10];
    const float* W2rcl = (const float*)d_in[11];
    const float* W2rcr = (const float*)d_in[12];
    const float* b2rc  = (const float*)d_in[13];
    const float* Wd1   = (const float*)d_in[14];
    const float* bd1   = (const float*)d_in[15];
    const float* Wd2   = (const float*)d_in[16];
    const float* bd2   = (const float*)d_in[17];
    const int*   e_cr  = (const int*)d_in[18];
    const int*   e_rc  = (const int*)d_in[19];
    const int*   e_lab = (const int*)d_in[20];
    const int E_ = in_sizes[18] / 2;
    const int L_ = in_sizes[20] / 2;

    uint4 *t_c4, *t_r4, *t_c4b, *t_r4b;
    float *s_r, *s_c, *h_r, *h_c, *u_r, *u_c;
    float *wc_crl, *wc_crr, *wc_rcl, *wc_rcr, *bc_r, *bc_c;
    int *dg_r, *dg_c, *off_r, *off_c, *cur_r, *cur_c, *csr_cr, *csr_rc, *bsum;
    cudaGetSymbolAddress((void**)&t_c4, g_t_c4);
    cudaGetSymbolAddress((void**)&t_r4, g_t_r4);
    cudaGetSymbolAddress((void**)&t_c4b, g_t_c4b);
    cudaGetSymbolAddress((void**)&t_r4b, g_t_r4b);
    cudaGetSymbolAddress((void**)&s_r, g_s_r);
    cudaGetSymbolAddress((void**)&s_c, g_s_c);
    cudaGetSymbolAddress((void**)&h_r, g_h_r);
    cudaGetSymbolAddress((void**)&h_c, g_h_c);
    cudaGetSymbolAddress((void**)&u_r, g_u_r);
    cudaGetSymbolAddress((void**)&u_c, g_u_c);
    cudaGetSymbolAddress((void**)&dg_r, g_dg_r);
    cudaGetSymbolAddress((void**)&dg_c, g_dg_c);
    cudaGetSymbolAddress((void**)&off_r, g_off_r);
    cudaGetSymbolAddress((void**)&off_c, g_off_c);
    cudaGetSymbolAddress((void**)&cur_r, g_cur_r);
    cudaGetSymbolAddress((void**)&cur_c, g_cur_c);
    cudaGetSymbolAddress((void**)&csr_cr, g_csr_cr);
    cudaGetSymbolAddress((void**)&csr_rc, g_csr_rc);
    cudaGetSymbolAddress((void**)&bsum, g_bsum);
    cudaGetSymbolAddress((void**)&wc_crl, g_wc_crl);
    cudaGetSymbolAddress((void**)&wc_crr, g_wc_crr);
    cudaGetSymbolAddress((void**)&wc_rcl, g_wc_rcl);
    cudaGetSymbolAddress((void**)&wc_rcr, g_wc_rcr);
    cudaGetSymbolAddress((void**)&bc_r, g_bc_r);
    cudaGetSymbolAddress((void**)&bc_c, g_bc_c);

    const uint2* t_c2  = (const uint2*)t_c4;
    const uint2* t_r2  = (const uint2*)t_r4;
    const uint2* t_c2b = (const uint2*)t_c4b;
    const uint2* t_r2b = (const uint2*)t_r4b;

    // streams + events (created once, on the uncaptured correctness call)
    static cudaStream_t s2 = nullptr, s3 = nullptr;
    static cudaEvent_t evFork = nullptr, evCSR = nullptr, evA2 = nullptr,
                       evG7 = nullptr, evA4 = nullptr;
    if (s2 == nullptr) {
        cudaStreamCreateWithFlags(&s2, cudaStreamNonBlocking);
        cudaStreamCreateWithFlags(&s3, cudaStreamNonBlocking);
        cudaEventCreateWithFlags(&evFork, cudaEventDisableTiming);
        cudaEventCreateWithFlags(&evCSR, cudaEventDisableTiming);
        cudaEventCreateWithFlags(&evA2, cudaEventDisableTiming);
        cudaEventCreateWithFlags(&evG7, cudaEventDisableTiming);
        cudaEventCreateWithFlags(&evA4, cudaEventDisableTiming);
    }

    const int NT = 256;
    const int gRow  = (NCN + NT - 1) / NT;
    const int gE2   = (2 * E_ + NT - 1) / NT;
    const int gZ2   = (2 * (NCN / 4) + NT - 1) / NT;
    const int gN16  = (NCN * 16 + NT - 1) / NT;
    const int gL16  = (L_ * 16 + NT - 1) / NT;

    const int* cr_s = e_cr;   const int* cr_d = e_cr + E_;
    const int* rc_s = e_rc;   const int* rc_d = e_rc + E_;
    const int* lb_r = e_lab;  const int* lb_c = e_lab + L_;

    const float* Wd_top = Wd1;
    const float* Wd_bot = Wd1 + HD * HD;

    // ======== FORK (main -> s2, s3) ========
    cudaEventRecord(evFork, 0);
    cudaStreamWaitEvent(s2, evFork, 0);
    cudaStreamWaitEvent(s3, evFork, 0);

    // ---- [1] s3: CSR chain -> evCSR ----
    zero2_k<<<gZ2, NT, 0, s3>>>((int4*)dg_r, (int4*)dg_c, NRN / 4);
    degree2_k<<<gE2, NT, 0, s3>>>(cr_d, dg_r, rc_d, dg_c, E_);
    scan_block2_k<<<2 * NSCANB, SCAN_BS, 0, s3>>>(dg_r, off_r, dg_c, off_c, bsum, NCN);
    scan_sums2_k<<<2, 1024, 0, s3>>>(bsum);
    scan_add_copy2_k<<<2 * NSCANB, SCAN_BS, 0, s3>>>(off_r, cur_r, off_c, cur_c, bsum, NCN);
    csr_fill2_k<<<gE2, NT, 0, s3>>>(cr_s, cr_d, cur_r, csr_cr, rc_s, rc_d, cur_c, csr_rc, E_);
    cudaEventRecord(evCSR, s3);

    // ---- [2] s2: G3, G4; wait evCSR; A2 -> evA2 ----
    gemm_nk_h<<<gRow, NT, 64 * HD * sizeof(float), s2>>>(x_r, W1rcl, t_r4, NRN, 64);
    gemm_nk  <<<gRow, NT, 128 * HD * sizeof(float), s2>>>(x_c, W1rcr, s_c, NCN, 128);
    cudaStreamWaitEvent(s2, evCSR, 0);
    aggregate16_k<<<gN16, NT, 0, s2>>>(t_r2, s_c, b1rc, off_c, dg_c, csr_rc, h_c, NCN, 1);
    cudaEventRecord(evA2, s2);

    // ---- [3] main: fold, G1, G2; wait evCSR; A1; G6, G7 -> evG7 ----
    fold_k<<<258, HD>>>(W2crl, W2crr, W2rcl, W2rcr, b2cr, b2rc, Wd_top, Wd_bot,
                        wc_crl, wc_crr, wc_rcl, wc_rcr, bc_r, bc_c);
    gemm_nk_h<<<gRow, NT, 128 * HD * sizeof(float)>>>(x_c, W1crl, t_c4, NCN, 128);
    gemm_nk  <<<gRow, NT,  64 * HD * sizeof(float)>>>(x_r, W1crr, s_r, NRN, 64);
    cudaStreamWaitEvent(0, evCSR, 0);
    aggregate16_k<<<gN16, NT>>>(t_c2, s_r, b1cr, off_r, dg_r, csr_cr, h_r, NRN, 1);
    gemm_nk  <<<gRow, NT, 64 * HD * sizeof(float)>>>(h_r, wc_crr, s_r, NRN, 64);
    gemm_nk_h<<<gRow, NT, 64 * HD * sizeof(float)>>>(h_r, wc_rcl, t_r4b, NRN, 64);
    cudaEventRecord(evG7, 0);

    // ---- [4] s2: G8; wait evG7; A4 -> evA4 ----
    gemm_nk<<<gRow, NT, 64 * HD * sizeof(float), s2>>>(h_c, wc_rcr, s_c, NCN, 64);
    cudaStreamWaitEvent(s2, evG7, 0);
    aggregate16_k<<<gN16, NT, 0, s2>>>(t_r2b, s_c, bc_c, off_c, dg_c, csr_rc, u_c, NCN, 0);
    cudaEventRecord(evA4, s2);

    // ---- [5] main: wait evA2; G5; A3; wait evA4; decode ----
    cudaStreamWaitEvent(0, evA2, 0);
    gemm_nk_h<<<gRow, NT, 64 * HD * sizeof(float)>>>(h_c, wc_crl, t_c4b, NCN, 64);
    aggregate16_k<<<gN16, NT>>>(t_c2b, s_r, bc_r, off_r, dg_r, csr_cr, u_r, NRN, 0);
    cudaStreamWaitEvent(0, evA4, 0);
    decode16_k<<<gL16, NT>>>(u_c, u_r, lb_r, lb_c, bd1, Wd2, bd2, (float*)d_out, L_);
}